// round 8
// baseline (speedup 1.0000x reference)
#include <cuda_runtime.h>
#include <cuda_fp16.h>

#define NPTS 1600
#define HIDC 64
#define TILE 256
#define NPART 25

__device__ float g_h[NPTS*HIDC];     // pre-norm hidden
__device__ float g_Q[NPTS*HIDC];
__device__ uint2 g_KVT[32*NPTS];     // [(head*4+d2)*NPTS + j] = {K half2, V half2}
__device__ float g_agg[NPTS*HIDC];   // attention output
__device__ float g_o[NPTS*HIDC];     // pre-norm output MLP
__device__ float g_part[NPART*8];    // partial stats
__device__ float g_stats[16];        // [0..3] mu_in [4..7] rs_in [8..11] mu_out [12..15] rs_out

__device__ __forceinline__ float leaky(float x) { return x >= 0.f ? x : 0.2f * x; }

// ---------------- K1: input MLP (pre-norm), smem-staged weights ----------------
__global__ __launch_bounds__(256) void k_in_mlp(
    const float* __restrict__ feat,
    const float* __restrict__ w1, const float* __restrict__ b1,
    const float* __restrict__ w2, const float* __restrict__ b2)
{
    __shared__ float sf[4][16];
    __shared__ float t1[4][68];
    __shared__ float wt[64*65];
    int tid = threadIdx.x;
    int r = tid >> 6, c = tid & 63;
    int row = blockIdx.x*4 + r;

    if (tid < 64) sf[tid >> 4][tid & 15] = feat[blockIdx.x*64 + tid];
#pragma unroll
    for (int i = 0; i < 4; i++) {
        int idx = i*256 + tid;
        int cc = idx >> 4, kk = idx & 15;
        wt[kk*65 + cc] = w1[idx];
    }
    __syncthreads();
    float a = __ldg(&b1[c]);
#pragma unroll
    for (int k = 0; k < 16; k++) a = fmaf(sf[r][k], wt[k*65 + c], a);
    t1[r][c] = leaky(a);
    __syncthreads();
#pragma unroll
    for (int i = 0; i < 16; i++) {
        int idx = i*256 + tid;
        int cc = idx >> 6, kk = idx & 63;
        wt[kk*65 + cc] = w2[idx];
    }
    __syncthreads();
    float a2 = __ldg(&b2[c]);
#pragma unroll
    for (int k = 0; k < 64; k += 4) {
        float4 h4 = *(const float4*)&t1[r][k];
        a2 = fmaf(h4.x, wt[(k  )*65 + c], a2);
        a2 = fmaf(h4.y, wt[(k+1)*65 + c], a2);
        a2 = fmaf(h4.z, wt[(k+2)*65 + c], a2);
        a2 = fmaf(h4.w, wt[(k+3)*65 + c], a2);
    }
    g_h[row*64 + c] = leaky(a2);
}

// ---------------- stats: parallel partial + combine ----------------
__global__ __launch_bounds__(256) void k_stats_part(int which)
{
    const float4* src = (const float4*)(which ? g_o : g_h);
    float s[4] = {0,0,0,0}, q[4] = {0,0,0,0};
#pragma unroll
    for (int k = 0; k < 4; k++) {
        int idx = blockIdx.x*1024 + k*256 + threadIdx.x;
        float4 v = src[idx];
        int g = (idx & 15) >> 2;
        s[g] += v.x + v.y + v.z + v.w;
        q[g] += v.x*v.x + v.y*v.y + v.z*v.z + v.w*v.w;
    }
    __shared__ float red[256][8];
#pragma unroll
    for (int g = 0; g < 4; g++) { red[threadIdx.x][g] = s[g]; red[threadIdx.x][4+g] = q[g]; }
    __syncthreads();
    for (int st = 128; st > 0; st >>= 1) {
        if (threadIdx.x < st)
#pragma unroll
            for (int k = 0; k < 8; k++) red[threadIdx.x][k] += red[threadIdx.x + st][k];
        __syncthreads();
    }
    if (threadIdx.x < 8) g_part[blockIdx.x*8 + threadIdx.x] = red[0][threadIdx.x];
}

__global__ __launch_bounds__(32) void k_stats_comb(int which)
{
    int off = which ? 8 : 0;
    int g = threadIdx.x;
    if (g < 4) {
        float s = 0.f, q = 0.f;
        for (int b = 0; b < NPART; b++) { s += g_part[b*8 + g]; q += g_part[b*8 + 4 + g]; }
        const float invn = 1.f / (NPTS * 16.f);
        float mu  = s * invn;
        float var = q * invn - mu*mu;
        g_stats[off + g]     = mu;
        g_stats[off + 4 + g] = rsqrtf(var + 1e-5f);
    }
}

// ---------------- K3: normalize + QKV (smem-staged; K,V fp16 interleaved transposed) ----------------
__global__ __launch_bounds__(256) void k_qkv(
    const float* __restrict__ wq, const float* __restrict__ bq,
    const float* __restrict__ wk, const float* __restrict__ bk,
    const float* __restrict__ wv, const float* __restrict__ bv,
    const float* __restrict__ gam, const float* __restrict__ bet)
{
    __shared__ float hn[4][68];
    __shared__ float wt[64*65];
    __shared__ float sK[4][64];
    __shared__ float sV[4][64];
    int tid = threadIdx.x;
    int r = tid >> 6, c = tid & 63;
    int row = blockIdx.x*4 + r;

    {
        int g = c >> 4;
        float x = g_h[row*64 + c];
        float v = (x - g_stats[g]) * g_stats[4+g];
        hn[r][c] = fmaf(v, __ldg(&gam[c]), __ldg(&bet[c]));
    }

    const float* Ws[3] = {wq, wk, wv};
    const float* Bs[3] = {bq, bk, bv};
#pragma unroll
    for (int mtx = 0; mtx < 3; mtx++) {
        __syncthreads();
#pragma unroll
        for (int i = 0; i < 16; i++) {
            int idx = i*256 + tid;
            int cc = idx >> 6, kk = idx & 63;
            wt[kk*65 + cc] = Ws[mtx][idx];
        }
        __syncthreads();
        float a = __ldg(&Bs[mtx][c]);
#pragma unroll
        for (int k = 0; k < 64; k += 4) {
            float4 h4 = *(const float4*)&hn[r][k];
            a = fmaf(h4.x, wt[(k  )*65 + c], a);
            a = fmaf(h4.y, wt[(k+1)*65 + c], a);
            a = fmaf(h4.z, wt[(k+2)*65 + c], a);
            a = fmaf(h4.w, wt[(k+3)*65 + c], a);
        }
        if (mtx == 0)      g_Q[row*64 + c] = a;
        else if (mtx == 1) sK[r][c] = a;
        else               sV[r][c] = a;
    }
    __syncthreads();
    if (tid < 128) {
        int rr = tid >> 5, cp = tid & 31;
        int rw = blockIdx.x*4 + rr;
        __half2 kh = __floats2half2_rn(sK[rr][2*cp], sK[rr][2*cp+1]);
        __half2 vh = __floats2half2_rn(sV[rr][2*cp], sV[rr][2*cp+1]);
        uint2 kv;
        kv.x = *(unsigned int*)&kh;
        kv.y = *(unsigned int*)&vh;
        g_KVT[cp*NPTS + rw] = kv;
    }
}

// ---------------- K4: fused pairwise geometry + conv + attention ----------------
// block = TWO queries (2b, 2b+1); 8 warps = 8 heads serving both queries.
__global__ __launch_bounds__(256, 2) void k_attn(
    const float* __restrict__ points, const float* __restrict__ nuv,
    const float* __restrict__ cw1, const float* __restrict__ cb1,
    const float* __restrict__ cw2, const float* __restrict__ cb2,
    const float* __restrict__ rls, const float* __restrict__ ra,
    const float* __restrict__ rb, const float* __restrict__ rc)
{
    const float INVS  = 0.11785113019775793f;   // 1/(sqrt(2)*6)
    const float SCALE = 0.3535533905932738f;    // 1/sqrt(8)
    int i0 = blockIdx.x * 2;
    int tid = threadIdx.x, warp = tid >> 5, lane = tid & 31;

    __shared__ uint4 sF1h[2][TILE];
    __shared__ float sWgt[2][TILE];
    __shared__ float sQ[128];
    __shared__ float sNuv[18], sPi[6];
    __shared__ float sw1[64], sb1[8], sra[32], srb[4], src[8], sInv2s2;

    if (tid < 64)  sw1[tid] = __ldg(&cw1[tid]);
    if (tid < 128) sQ[tid]  = g_Q[i0*64 + tid];
    if (tid < 8)  { sb1[tid] = __ldg(&cb1[tid]); src[tid] = __ldg(&rc[tid]); }
    if (tid < 32) sra[tid] = __ldg(&ra[tid]);
    if (tid < 4)  srb[tid] = __ldg(&rb[tid]);
    if (tid < 18) sNuv[tid] = nuv[i0*9 + tid];
    if (tid < 6)  sPi[tid]  = points[i0*3 + tid];
    if (tid == 0) { float sg = fmaxf(__expf(__ldg(&rls[0])), 1e-6f); sInv2s2 = 0.5f/(sg*sg); }
    __syncthreads();

    // head-private: conv_w2 half2 c-pair packed (shared by both queries), Q per query
    __half2 w2h[32], b2h[4], qh2[2][4];
#pragma unroll
    for (int cp = 0; cp < 4; cp++) {
        b2h[cp] = __floats2half2_rn(__ldg(&cb2[warp*8 + 2*cp]), __ldg(&cb2[warp*8 + 2*cp + 1]));
#pragma unroll
        for (int q = 0; q < 2; q++)
            qh2[q][cp] = __floats2half2_rn(sQ[q*64 + warp*8 + 2*cp] * SCALE,
                                           sQ[q*64 + warp*8 + 2*cp + 1] * SCALE);
#pragma unroll
        for (int k = 0; k < 8; k++)
            w2h[cp*8 + k] = __floats2half2_rn(__ldg(&cw2[(warp*8 + 2*cp)*8 + k]),
                                              __ldg(&cw2[(warp*8 + 2*cp + 1)*8 + k]));
    }
    float den[2] = {0.f, 0.f};
    float acc[2][8];
#pragma unroll
    for (int q = 0; q < 2; q++)
#pragma unroll
        for (int c = 0; c < 8; c++) acc[q][c] = 0.f;

    const uint2* KVTb = &g_KVT[warp*4*NPTS];

    for (int tb = 0; tb < NPTS; tb += TILE) {
        int j = tb + tid;
        if (j < NPTS) {
            float px = points[j*3+0], py = points[j*3+1], pz = points[j*3+2];
            float n0 = nuv[j*9+0], n1 = nuv[j*9+1], n2 = nuv[j*9+2];
#pragma unroll
            for (int q = 0; q < 2; q++) {
                float dx = (px - sPi[q*3+0]) * INVS;
                float dy = (py - sPi[q*3+1]) * INVS;
                float dz = (pz - sPi[q*3+2]) * INVS;
                float ndot = sNuv[q*9+0]*n0 + sNuv[q*9+1]*n1 + sNuv[q*9+2]*n2;
                float u = 2.f - ndot;
                float d2 = (dx*dx + dy*dy + dz*dz) * u * u;
                float t = 1.f / (1.f + d2 * (1.f/3.f));
                sWgt[q][tid] = t*t*t;
                float bd = sqrtf(d2);
                float X[8];
                X[0] = sNuv[q*9+0]*dx + sNuv[q*9+1]*dy + sNuv[q*9+2]*dz;
                X[1] = sNuv[q*9+3]*dx + sNuv[q*9+4]*dy + sNuv[q*9+5]*dz;
                X[2] = sNuv[q*9+6]*dx + sNuv[q*9+7]*dy + sNuv[q*9+8]*dz;
                X[3] = ndot;
                float rp0 = srb[0], rp1 = srb[1], rp2 = srb[2], rp3 = srb[3];
#pragma unroll
                for (int r = 0; r < 8; r++) {
                    float dd = bd - src[r];
                    float e = __expf(-dd*dd * sInv2s2);
                    rp0 = fmaf(e, sra[0*8+r], rp0);
                    rp1 = fmaf(e, sra[1*8+r], rp1);
                    rp2 = fmaf(e, sra[2*8+r], rp2);
                    rp3 = fmaf(e, sra[3*8+r], rp3);
                }
                X[4] = rp0; X[5] = rp1; X[6] = rp2; X[7] = rp3;
                float F[8];
#pragma unroll
                for (int c = 0; c < 8; c++) {
                    float a = sb1[c];
#pragma unroll
                    for (int k = 0; k < 8; k++) a = fmaf(X[k], sw1[c*8+k], a);
                    F[c] = fmaxf(a, 0.f);
                }
                uint4 pkv;
                __half2 h01 = __floats2half2_rn(F[0], F[1]);
                __half2 h23 = __floats2half2_rn(F[2], F[3]);
                __half2 h45 = __floats2half2_rn(F[4], F[5]);
                __half2 h67 = __floats2half2_rn(F[6], F[7]);
                pkv.x = *(unsigned int*)&h01; pkv.y = *(unsigned int*)&h23;
                pkv.z = *(unsigned int*)&h45; pkv.w = *(unsigned int*)&h67;
                sF1h[q][tid] = pkv;
            }
        }
        __syncthreads();
        int cnt = min(TILE, NPTS - tb);
#pragma unroll 2
        for (int jj = lane; jj < cnt; jj += 32) {
            int j = tb + jj;
            uint2 kva = __ldg(&KVTb[j]);
            uint2 kvb = __ldg(&KVTb[NPTS + j]);
            uint2 kvc = __ldg(&KVTb[2*NPTS + j]);
            uint2 kvd = __ldg(&KVTb[3*NPTS + j]);
            __half2 ka = *(const __half2*)&kva.x, kb = *(const __half2*)&kvb.x;
            __half2 kc = *(const __half2*)&kvc.x, kd = *(const __half2*)&kvd.x;
            __half2 va = *(const __half2*)&kva.y, vb = *(const __half2*)&kvb.y;
            __half2 vc = *(const __half2*)&kvc.y, vd = *(const __half2*)&kvd.y;
#pragma unroll
            for (int q = 0; q < 2; q++) {
                uint4 fu = sF1h[q][jj];
                float wgt = sWgt[q][jj];
                __half2 t0 = __hmul2(qh2[q][0], ka); t0 = __hfma2(qh2[q][1], kb, t0);
                __half2 t1 = __hmul2(qh2[q][2], kc); t1 = __hfma2(qh2[q][3], kd, t1);
                float2 sf = __half22float2(__hadd2(t0, t1));
                float e = __expf(sf.x + sf.y);
                den[q] += e;
                float ew = e * wgt;

                __half2 h01 = *(__half2*)&fu.x, h23 = *(__half2*)&fu.y;
                __half2 h45 = *(__half2*)&fu.z, h67 = *(__half2*)&fu.w;
                __half2 fb8[8];
                fb8[0] = __low2half2(h01); fb8[1] = __high2half2(h01);
                fb8[2] = __low2half2(h23); fb8[3] = __high2half2(h23);
                fb8[4] = __low2half2(h45); fb8[5] = __high2half2(h45);
                fb8[6] = __low2half2(h67); fb8[7] = __high2half2(h67);
                __half2 a0 = b2h[0], a1 = b2h[1], a2 = b2h[2], a3 = b2h[3];
#pragma unroll
                for (int k = 0; k < 8; k++) {
                    a0 = __hfma2(fb8[k], w2h[k],    a0);
                    a1 = __hfma2(fb8[k], w2h[8+k],  a1);
                    a2 = __hfma2(fb8[k], w2h[16+k], a2);
                    a3 = __hfma2(fb8[k], w2h[24+k], a3);
                }
                const __half2 zero2 = __float2half2_rn(0.f);
                a0 = __hmax2(a0, zero2); a1 = __hmax2(a1, zero2);
                a2 = __hmax2(a2, zero2); a3 = __hmax2(a3, zero2);
                {
                    float2 p = __half22float2(__hmul2(a0, va));
                    acc[q][0] = fmaf(ew, p.x, acc[q][0]); acc[q][1] = fmaf(ew, p.y, acc[q][1]);
                }
                {
                    float2 p = __half22float2(__hmul2(a1, vb));
                    acc[q][2] = fmaf(ew, p.x, acc[q][2]); acc[q][3] = fmaf(ew, p.y, acc[q][3]);
                }
                {
                    float2 p = __half22float2(__hmul2(a2, vc));
                    acc[q][4] = fmaf(ew, p.x, acc[q][4]); acc[q][5] = fmaf(ew, p.y, acc[q][5]);
                }
                {
                    float2 p = __half22float2(__hmul2(a3, vd));
                    acc[q][6] = fmaf(ew, p.x, acc[q][6]); acc[q][7] = fmaf(ew, p.y, acc[q][7]);
                }
            }
        }
        __syncthreads();
    }
    // warp reductions per query
#pragma unroll
    for (int q = 0; q < 2; q++) {
        float denom = den[q];
#pragma unroll
        for (int o = 16; o > 0; o >>= 1) denom += __shfl_xor_sync(0xffffffffu, denom, o);
#pragma unroll
        for (int c = 0; c < 8; c++)
#pragma unroll
            for (int o = 16; o > 0; o >>= 1) acc[q][c] += __shfl_xor_sync(0xffffffffu, acc[q][c], o);
        if (lane == 0) {
            float inv = 1.f / denom;
#pragma unroll
            for (int c = 0; c < 8; c++) g_agg[(i0 + q)*64 + warp*8 + c] = acc[q][c] * inv;
        }
    }
}

// ---------------- K5: output MLP (pre-norm), smem-staged ----------------
__global__ __launch_bounds__(256) void k_out_mlp(
    const float* __restrict__ w1, const float* __restrict__ b1,
    const float* __restrict__ w2, const float* __restrict__ b2)
{
    __shared__ float a0[4][68];
    __shared__ float t1[4][68];
    __shared__ float wt[64*65];
    int tid = threadIdx.x;
    int r = tid >> 6, c = tid & 63;
    int row = blockIdx.x*4 + r;

    a0[r][c] = g_agg[row*64 + c];
#pragma unroll
    for (int i = 0; i < 16; i++) {
        int idx = i*256 + tid;
        int cc = idx >> 6, kk = idx & 63;
        wt[kk*65 + cc] = w1[idx];
    }
    __syncthreads();
    float a = __ldg(&b1[c]);
#pragma unroll
    for (int k = 0; k < 64; k += 4) {
        float4 h4 = *(const float4*)&a0[r][k];
        a = fmaf(h4.x, wt[(k  )*65 + c], a);
        a = fmaf(h4.y, wt[(k+1)*65 + c], a);
        a = fmaf(h4.z, wt[(k+2)*65 + c], a);
        a = fmaf(h4.w, wt[(k+3)*65 + c], a);
    }
    t1[r][c] = leaky(a);
    __syncthreads();
#pragma unroll
    for (int i = 0; i < 16; i++) {
        int idx = i*256 + tid;
        int cc = idx >> 6, kk = idx & 63;
        wt[kk*65 + cc] = w2[idx];
    }
    __syncthreads();
    float a2 = __ldg(&b2[c]);
#pragma unroll
    for (int k = 0; k < 64; k += 4) {
        float4 h4 = *(const float4*)&t1[r][k];
        a2 = fmaf(h4.x, wt[(k  )*65 + c], a2);
        a2 = fmaf(h4.y, wt[(k+1)*65 + c], a2);
        a2 = fmaf(h4.z, wt[(k+2)*65 + c], a2);
        a2 = fmaf(h4.w, wt[(k+3)*65 + c], a2);
    }
    g_o[row*64 + c] = leaky(a2);
}

// ---------------- K7: final norm + residual ----------------
__global__ __launch_bounds__(256) void k_finalize(
    const float* __restrict__ feat,
    const float* __restrict__ gam, const float* __restrict__ bet,
    const float* __restrict__ wres, const float* __restrict__ bres,
    float* __restrict__ out)
{
    int idx = blockIdx.x * 256 + threadIdx.x;
    int row = idx >> 6, c = idx & 63, g = c >> 4;
    float x = (g_o[idx] - g_stats[8+g]) * g_stats[12+g];
    x = fmaf(x, __ldg(&gam[c]), __ldg(&bet[c]));
    float a = __ldg(&bres[c]);
#pragma unroll
    for (int k4 = 0; k4 < 4; k4++) {
        float4 f = __ldg((const float4*)&feat[row*16 + k4*4]);
        float4 w = __ldg((const float4*)&wres[c*16 + k4*4]);
        a = fmaf(f.x,w.x,a); a = fmaf(f.y,w.y,a); a = fmaf(f.z,w.z,a); a = fmaf(f.w,w.w,a);
    }
    out[idx] = x + a;
}

extern "C" void kernel_launch(void* const* d_in, const int* in_sizes, int n_in,
                              void* d_out, int out_size)
{
    const float* points   = (const float*)d_in[0];
    const float* nuv      = (const float*)d_in[1];
    const float* features = (const float*)d_in[2];
    const float* w_in1    = (const float*)d_in[3];
    const float* b_in1    = (const float*)d_in[4];
    const float* w_in2    = (const float*)d_in[5];
    const float* b_in2    = (const float*)d_in[6];
    const float* g_in     = (const float*)d_in[7];
    const float* be_in    = (const float*)d_in[8];
    const float* wq       = (const float*)d_in[9];
    const float* bq       = (const float*)d_in[10];
    const float* wk       = (const float*)d_in[11];
    const float* bk       = (const float*)d_in[12];
    const float* wv       = (const float*)d_in[13];
    const float* bv       = (const float*)d_in[14];
    const float* conv_w1  = (const float*)d_in[15];
    const float* conv_b1  = (const float*)d_in[16];
    const float* conv_w2  = (const float*)d_in[17];
    const float* conv_b2  = (const float*)d_in[18];
    const float* rls      = (const float*)d_in[19];
    const float* rbf_a    = (const float*)d_in[20];
    const float* rbf_b    = (const float*)d_in[21];
    const float* rbf_c    = (const float*)d_in[22];
    const float* w_o1     = (const float*)d_in[23];
    const float* b_o1     = (const float*)d_in[24];
    const float* w_o2     = (const float*)d_in[25];
    const float* b_o2     = (const float*)d_in[26];
    const float* g_out    = (const float*)d_in[27];
    const float* be_out   = (const float*)d_in[28];
    const float* w_res    = (const float*)d_in[29];
    const float* b_res    = (const float*)d_in[30];

    k_in_mlp<<<NPTS/4, 256>>>(features, w_in1, b_in1, w_in2, b_in2);
    k_stats_part<<<NPART, 256>>>(0);
    k_stats_comb<<<1, 32>>>(0);
    k_qkv<<<NPTS/4, 256>>>(wq, bq, wk, bk, wv, bv, g_in, be_in);
    k_attn<<<NPTS/2, 256>>>(points, nuv, conv_w1, conv_b1, conv_w2, conv_b2,
                            rls, rbf_a, rbf_b, rbf_c);
    k_out_mlp<<<NPTS/4, 256>>>(w_o1, b_o1, w_o2, b_o2);
    k_stats_part<<<NPART, 256>>>(1);
    k_stats_comb<<<1, 32>>>(1);
    k_finalize<<<NPTS*64/256, 256>>>(features, g_out, be_out, w_res, b_res, (float*)d_out);
}

// round 9
// speedup vs baseline: 1.2578x; 1.2578x over previous
#include <cuda_runtime.h>
#include <cuda_fp16.h>

#define NPTS 1600
#define HIDC 64
#define TILE 256
#define NPART 25

__device__ float g_h[NPTS*HIDC];     // pre-norm hidden
__device__ float g_Q[NPTS*HIDC];
__device__ uint4 g_KV4[16*NPTS];     // [(head*2+p)*NPTS + j] = {K01,K23,V01,V23} fp16
__device__ float4 g_p4[NPTS];        // {px,py,pz,n0}
__device__ float2 g_n2[NPTS];        // {n1,n2}
__device__ float g_agg[NPTS*HIDC];   // attention output
__device__ float g_o[NPTS*HIDC];     // pre-norm output MLP
__device__ float g_part[NPART*8];    // partial stats
__device__ float g_stats[16];        // [0..3] mu_in [4..7] rs_in [8..11] mu_out [12..15] rs_out

__device__ __forceinline__ float leaky(float x) { return x >= 0.f ? x : 0.2f * x; }

// ---------------- K1: input MLP (pre-norm), smem-staged weights ----------------
__global__ __launch_bounds__(256) void k_in_mlp(
    const float* __restrict__ feat,
    const float* __restrict__ w1, const float* __restrict__ b1,
    const float* __restrict__ w2, const float* __restrict__ b2)
{
    __shared__ float sf[4][16];
    __shared__ float t1[4][68];
    __shared__ float wt[64*65];
    int tid = threadIdx.x;
    int r = tid >> 6, c = tid & 63;
    int row = blockIdx.x*4 + r;

    if (tid < 64) sf[tid >> 4][tid & 15] = feat[blockIdx.x*64 + tid];
#pragma unroll
    for (int i = 0; i < 4; i++) {
        int idx = i*256 + tid;
        int cc = idx >> 4, kk = idx & 15;
        wt[kk*65 + cc] = w1[idx];
    }
    __syncthreads();
    float a = __ldg(&b1[c]);
#pragma unroll
    for (int k = 0; k < 16; k++) a = fmaf(sf[r][k], wt[k*65 + c], a);
    t1[r][c] = leaky(a);
    __syncthreads();
#pragma unroll
    for (int i = 0; i < 16; i++) {
        int idx = i*256 + tid;
        int cc = idx >> 6, kk = idx & 63;
        wt[kk*65 + cc] = w2[idx];
    }
    __syncthreads();
    float a2 = __ldg(&b2[c]);
#pragma unroll
    for (int k = 0; k < 64; k += 4) {
        float4 h4 = *(const float4*)&t1[r][k];
        a2 = fmaf(h4.x, wt[(k  )*65 + c], a2);
        a2 = fmaf(h4.y, wt[(k+1)*65 + c], a2);
        a2 = fmaf(h4.z, wt[(k+2)*65 + c], a2);
        a2 = fmaf(h4.w, wt[(k+3)*65 + c], a2);
    }
    g_h[row*64 + c] = leaky(a2);
}

// ---------------- stats: parallel partial + combine (+ geometry pack on pass 0) ----------------
__global__ __launch_bounds__(256) void k_stats_part(
    int which, const float* __restrict__ points, const float* __restrict__ nuv)
{
    if (which == 0) {
        int p = blockIdx.x*256 + threadIdx.x;
        if (p < NPTS) {
            g_p4[p] = make_float4(points[p*3+0], points[p*3+1], points[p*3+2], nuv[p*9+0]);
            g_n2[p] = make_float2(nuv[p*9+1], nuv[p*9+2]);
        }
    }
    const float4* src = (const float4*)(which ? g_o : g_h);
    float s[4] = {0,0,0,0}, q[4] = {0,0,0,0};
#pragma unroll
    for (int k = 0; k < 4; k++) {
        int idx = blockIdx.x*1024 + k*256 + threadIdx.x;
        float4 v = src[idx];
        int g = (idx & 15) >> 2;
        s[g] += v.x + v.y + v.z + v.w;
        q[g] += v.x*v.x + v.y*v.y + v.z*v.z + v.w*v.w;
    }
    __shared__ float red[256][8];
#pragma unroll
    for (int g = 0; g < 4; g++) { red[threadIdx.x][g] = s[g]; red[threadIdx.x][4+g] = q[g]; }
    __syncthreads();
    for (int st = 128; st > 0; st >>= 1) {
        if (threadIdx.x < st)
#pragma unroll
            for (int k = 0; k < 8; k++) red[threadIdx.x][k] += red[threadIdx.x + st][k];
        __syncthreads();
    }
    if (threadIdx.x < 8) g_part[blockIdx.x*8 + threadIdx.x] = red[0][threadIdx.x];
}

__global__ __launch_bounds__(32) void k_stats_comb(int which)
{
    int off = which ? 8 : 0;
    int g = threadIdx.x;
    if (g < 4) {
        float s = 0.f, q = 0.f;
        for (int b = 0; b < NPART; b++) { s += g_part[b*8 + g]; q += g_part[b*8 + 4 + g]; }
        const float invn = 1.f / (NPTS * 16.f);
        float mu  = s * invn;
        float var = q * invn - mu*mu;
        g_stats[off + g]     = mu;
        g_stats[off + 4 + g] = rsqrtf(var + 1e-5f);
    }
}

// ---------------- K3: normalize + QKV (smem-staged; K,V fp16 packed uint4, transposed) ----------------
__global__ __launch_bounds__(256) void k_qkv(
    const float* __restrict__ wq, const float* __restrict__ bq,
    const float* __restrict__ wk, const float* __restrict__ bk,
    const float* __restrict__ wv, const float* __restrict__ bv,
    const float* __restrict__ gam, const float* __restrict__ bet)
{
    __shared__ float hn[4][68];
    __shared__ float wt[64*65];
    __shared__ float sK[4][64];
    __shared__ float sV[4][64];
    int tid = threadIdx.x;
    int r = tid >> 6, c = tid & 63;
    int row = blockIdx.x*4 + r;

    {
        int g = c >> 4;
        float x = g_h[row*64 + c];
        float v = (x - g_stats[g]) * g_stats[4+g];
        hn[r][c] = fmaf(v, __ldg(&gam[c]), __ldg(&bet[c]));
    }

    const float* Ws[3] = {wq, wk, wv};
    const float* Bs[3] = {bq, bk, bv};
#pragma unroll
    for (int mtx = 0; mtx < 3; mtx++) {
        __syncthreads();
#pragma unroll
        for (int i = 0; i < 16; i++) {
            int idx = i*256 + tid;
            int cc = idx >> 6, kk = idx & 63;
            wt[kk*65 + cc] = Ws[mtx][idx];
        }
        __syncthreads();
        float a = __ldg(&Bs[mtx][c]);
#pragma unroll
        for (int k = 0; k < 64; k += 4) {
            float4 h4 = *(const float4*)&hn[r][k];
            a = fmaf(h4.x, wt[(k  )*65 + c], a);
            a = fmaf(h4.y, wt[(k+1)*65 + c], a);
            a = fmaf(h4.z, wt[(k+2)*65 + c], a);
            a = fmaf(h4.w, wt[(k+3)*65 + c], a);
        }
        if (mtx == 0)      g_Q[row*64 + c] = a;
        else if (mtx == 1) sK[r][c] = a;
        else               sV[r][c] = a;
    }
    __syncthreads();
    // pack: 64 threads = 4 rows x 16 quad-groups; g_KV4[g4*NPTS + row] = {K01,K23,V01,V23}
    if (tid < 64) {
        int rr = tid >> 4, g4 = tid & 15;
        int rw = blockIdx.x*4 + rr;
        __half2 k01 = __floats2half2_rn(sK[rr][4*g4+0], sK[rr][4*g4+1]);
        __half2 k23 = __floats2half2_rn(sK[rr][4*g4+2], sK[rr][4*g4+3]);
        __half2 v01 = __floats2half2_rn(sV[rr][4*g4+0], sV[rr][4*g4+1]);
        __half2 v23 = __floats2half2_rn(sV[rr][4*g4+2], sV[rr][4*g4+3]);
        uint4 u;
        u.x = *(unsigned int*)&k01; u.y = *(unsigned int*)&k23;
        u.z = *(unsigned int*)&v01; u.w = *(unsigned int*)&v23;
        g_KV4[g4*NPTS + rw] = u;
    }
}

// ---------------- K4: fused pairwise geometry + conv + attention ----------------
__device__ __forceinline__ void attn_body(
    int j, const uint4 fu, const float wgt, const uint4* __restrict__ KVb,
    const __half2* qh2, const __half2* w2h, const __half2* b2h,
    float* acc, float& denom)
{
    uint4 u0 = __ldg(&KVb[j]);
    uint4 u1 = __ldg(&KVb[NPTS + j]);
    __half2 t0 = __hmul2(qh2[0], *(const __half2*)&u0.x);
    t0 = __hfma2(qh2[1], *(const __half2*)&u0.y, t0);
    __half2 t1 = __hmul2(qh2[2], *(const __half2*)&u1.x);
    t1 = __hfma2(qh2[3], *(const __half2*)&u1.y, t1);
    float2 sf = __half22float2(__hadd2(t0, t1));
    float e = __expf(sf.x + sf.y);
    denom += e;
    float ew = e * wgt;

    __half2 h01 = *(const __half2*)&fu.x, h23 = *(const __half2*)&fu.y;
    __half2 h45 = *(const __half2*)&fu.z, h67 = *(const __half2*)&fu.w;
    __half2 fb8[8];
    fb8[0] = __low2half2(h01); fb8[1] = __high2half2(h01);
    fb8[2] = __low2half2(h23); fb8[3] = __high2half2(h23);
    fb8[4] = __low2half2(h45); fb8[5] = __high2half2(h45);
    fb8[6] = __low2half2(h67); fb8[7] = __high2half2(h67);
    __half2 a0 = b2h[0], a1 = b2h[1], a2 = b2h[2], a3 = b2h[3];
#pragma unroll
    for (int k = 0; k < 8; k++) {
        a0 = __hfma2(fb8[k], w2h[k],    a0);
        a1 = __hfma2(fb8[k], w2h[8+k],  a1);
        a2 = __hfma2(fb8[k], w2h[16+k], a2);
        a3 = __hfma2(fb8[k], w2h[24+k], a3);
    }
    const __half2 zero2 = __float2half2_rn(0.f);
    a0 = __hmax2(a0, zero2); a1 = __hmax2(a1, zero2);
    a2 = __hmax2(a2, zero2); a3 = __hmax2(a3, zero2);
    {
        float2 p = __half22float2(__hmul2(a0, *(const __half2*)&u0.z));
        acc[0] = fmaf(ew, p.x, acc[0]); acc[1] = fmaf(ew, p.y, acc[1]);
    }
    {
        float2 p = __half22float2(__hmul2(a1, *(const __half2*)&u0.w));
        acc[2] = fmaf(ew, p.x, acc[2]); acc[3] = fmaf(ew, p.y, acc[3]);
    }
    {
        float2 p = __half22float2(__hmul2(a2, *(const __half2*)&u1.z));
        acc[4] = fmaf(ew, p.x, acc[4]); acc[5] = fmaf(ew, p.y, acc[5]);
    }
    {
        float2 p = __half22float2(__hmul2(a3, *(const __half2*)&u1.w));
        acc[6] = fmaf(ew, p.x, acc[6]); acc[7] = fmaf(ew, p.y, acc[7]);
    }
}

__global__ __launch_bounds__(256, 2) void k_attn(
    const float* __restrict__ points, const float* __restrict__ nuv,
    const float* __restrict__ cw1, const float* __restrict__ cb1,
    const float* __restrict__ cw2, const float* __restrict__ cb2,
    const float* __restrict__ rls, const float* __restrict__ ra,
    const float* __restrict__ rb, const float* __restrict__ rc)
{
    const float INVS  = 0.11785113019775793f;   // 1/(sqrt(2)*6)
    const float SCALE = 0.3535533905932738f;    // 1/sqrt(8)
    int i = blockIdx.x;
    int tid = threadIdx.x, warp = tid >> 5, lane = tid & 31;

    __shared__ uint4 sF1h[TILE];
    __shared__ float sWgt[TILE];
    __shared__ float sQ[64];
    __shared__ float sNuv[9], sPi[3];
    __shared__ float sw1[64], sb1[8], sra[32], srb[4], src[8], sInv2s2;

    if (tid < 64) { sw1[tid] = __ldg(&cw1[tid]); sQ[tid] = g_Q[i*64 + tid]; }
    if (tid < 8)  { sb1[tid] = __ldg(&cb1[tid]); src[tid] = __ldg(&rc[tid]); }
    if (tid < 32) sra[tid] = __ldg(&ra[tid]);
    if (tid < 4)  srb[tid] = __ldg(&rb[tid]);
    if (tid < 9)  sNuv[tid] = nuv[i*9 + tid];
    if (tid < 3)  sPi[tid]  = points[i*3 + tid];
    if (tid == 0) { float sg = fmaxf(__expf(__ldg(&rls[0])), 1e-6f); sInv2s2 = 0.5f/(sg*sg); }
    __syncthreads();

    // head-private: conv_w2 half2 c-pair packed, bias, Q half2 with scale folded
    __half2 w2h[32], b2h[4], qh2[4];
#pragma unroll
    for (int cp = 0; cp < 4; cp++) {
        b2h[cp] = __floats2half2_rn(__ldg(&cb2[warp*8 + 2*cp]), __ldg(&cb2[warp*8 + 2*cp + 1]));
        qh2[cp] = __floats2half2_rn(sQ[warp*8 + 2*cp] * SCALE, sQ[warp*8 + 2*cp + 1] * SCALE);
#pragma unroll
        for (int k = 0; k < 8; k++)
            w2h[cp*8 + k] = __floats2half2_rn(__ldg(&cw2[(warp*8 + 2*cp)*8 + k]),
                                              __ldg(&cw2[(warp*8 + 2*cp + 1)*8 + k]));
    }
    float denom = 0.f;
    float acc[8];
#pragma unroll
    for (int c = 0; c < 8; c++) acc[c] = 0.f;

    const uint4* KVb = &g_KV4[warp*2*NPTS];

    for (int tb = 0; tb < NPTS; tb += TILE) {
        int j = tb + tid;
        if (j < NPTS) {
            float4 pj = g_p4[j];
            float2 nj = g_n2[j];
            float dx = (pj.x - sPi[0]) * INVS;
            float dy = (pj.y - sPi[1]) * INVS;
            float dz = (pj.z - sPi[2]) * INVS;
            float ndot = sNuv[0]*pj.w + sNuv[1]*nj.x + sNuv[2]*nj.y;
            float u = 2.f - ndot;
            float d2 = (dx*dx + dy*dy + dz*dz) * u * u;
            float t = 1.f / (1.f + d2 * (1.f/3.f));
            sWgt[tid] = t*t*t;
            float bd = sqrtf(d2);
            float X[8];
            X[0] = sNuv[0]*dx + sNuv[1]*dy + sNuv[2]*dz;
            X[1] = sNuv[3]*dx + sNuv[4]*dy + sNuv[5]*dz;
            X[2] = sNuv[6]*dx + sNuv[7]*dy + sNuv[8]*dz;
            X[3] = ndot;
            float rp0 = srb[0], rp1 = srb[1], rp2 = srb[2], rp3 = srb[3];
#pragma unroll
            for (int r = 0; r < 8; r++) {
                float dd = bd - src[r];
                float e = __expf(-dd*dd * sInv2s2);
                rp0 = fmaf(e, sra[0*8+r], rp0);
                rp1 = fmaf(e, sra[1*8+r], rp1);
                rp2 = fmaf(e, sra[2*8+r], rp2);
                rp3 = fmaf(e, sra[3*8+r], rp3);
            }
            X[4] = rp0; X[5] = rp1; X[6] = rp2; X[7] = rp3;
            float F[8];
#pragma unroll
            for (int c = 0; c < 8; c++) {
                float a = sb1[c];
#pragma unroll
                for (int k = 0; k < 8; k++) a = fmaf(X[k], sw1[c*8+k], a);
                F[c] = fmaxf(a, 0.f);
            }
            uint4 pkv;
            __half2 h01 = __floats2half2_rn(F[0], F[1]);
            __half2 h23 = __floats2half2_rn(F[2], F[3]);
            __half2 h45 = __floats2half2_rn(F[4], F[5]);
            __half2 h67 = __floats2half2_rn(F[6], F[7]);
            pkv.x = *(unsigned int*)&h01; pkv.y = *(unsigned int*)&h23;
            pkv.z = *(unsigned int*)&h45; pkv.w = *(unsigned int*)&h67;
            sF1h[tid] = pkv;
        }
        __syncthreads();
        int cnt = min(TILE, NPTS - tb);
        if (cnt == TILE) {
#pragma unroll 4
            for (int it = 0; it < TILE/32; it++) {
                int jj = it*32 + lane;
                attn_body(tb + jj, sF1h[jj], sWgt[jj], KVb, qh2, w2h, b2h, acc, denom);
            }
        } else {
#pragma unroll 2
            for (int it = 0; it < 2; it++) {
                int jj = it*32 + lane;
                if (jj < cnt)
                    attn_body(tb + jj, sF1h[jj], sWgt[jj], KVb, qh2, w2h, b2h, acc, denom);
            }
        }
        __syncthreads();
    }
    // warp reductions
#pragma unroll
    for (int o = 16; o > 0; o >>= 1) denom += __shfl_xor_sync(0xffffffffu, denom, o);
#pragma unroll
    for (int c = 0; c < 8; c++)
#pragma unroll
        for (int o = 16; o > 0; o >>= 1) acc[c] += __shfl_xor_sync(0xffffffffu, acc[c], o);
    if (lane == 0) {
        float inv = 1.f / denom;
#pragma unroll
        for (int c = 0; c < 8; c++) g_agg[i*64 + warp*8 + c] = acc[c] * inv;
    }
}

// ---------------- K5: output MLP (pre-norm), smem-staged ----------------
__global__ __launch_bounds__(256) void k_out_mlp(
    const float* __restrict__ w1, const float* __restrict__ b1,
    const float* __restrict__ w2, const float* __restrict__ b2)
{
    __shared__ float a0[4][68];
    __shared__ float t1[4][68];
    __shared__ float wt[64*65];
    int tid = threadIdx.x;
    int r = tid >> 6, c = tid & 63;
    int row = blockIdx.x*4 + r;

    a0[r][c] = g_agg[row*64 + c];
#pragma unroll
    for (int i = 0; i < 16; i++) {
        int idx = i*256 + tid;
        int cc = idx >> 6, kk = idx & 63;
        wt[kk*65 + cc] = w1[idx];
    }
    __syncthreads();
    float a = __ldg(&b1[c]);
#pragma unroll
    for (int k = 0; k < 64; k += 4) {
        float4 h4 = *(const float4*)&a0[r][k];
        a = fmaf(h4.x, wt[(k  )*65 + c], a);
        a = fmaf(h4.y, wt[(k+1)*65 + c], a);
        a = fmaf(h4.z, wt[(k+2)*65 + c], a);
        a = fmaf(h4.w, wt[(k+3)*65 + c], a);
    }
    t1[r][c] = leaky(a);
    __syncthreads();
#pragma unroll
    for (int i = 0; i < 16; i++) {
        int idx = i*256 + tid;
        int cc = idx >> 6, kk = idx & 63;
        wt[kk*65 + cc] = w2[idx];
    }
    __syncthreads();
    float a2 = __ldg(&b2[c]);
#pragma unroll
    for (int k = 0; k < 64; k += 4) {
        float4 h4 = *(const float4*)&t1[r][k];
        a2 = fmaf(h4.x, wt[(k  )*65 + c], a2);
        a2 = fmaf(h4.y, wt[(k+1)*65 + c], a2);
        a2 = fmaf(h4.z, wt[(k+2)*65 + c], a2);
        a2 = fmaf(h4.w, wt[(k+3)*65 + c], a2);
    }
    g_o[row*64 + c] = leaky(a2);
}

// ---------------- K7: final norm + residual ----------------
__global__ __launch_bounds__(256) void k_finalize(
    const float* __restrict__ feat,
    const float* __restrict__ gam, const float* __restrict__ bet,
    const float* __restrict__ wres, const float* __restrict__ bres,
    float* __restrict__ out)
{
    int idx = blockIdx.x * 256 + threadIdx.x;
    int row = idx >> 6, c = idx & 63, g = c >> 4;
    float x = (g_o[idx] - g_stats[8+g]) * g_stats[12+g];
    x = fmaf(x, __ldg(&gam[c]), __ldg(&bet[c]));
    float a = __ldg(&bres[c]);
#pragma unroll
    for (int k4 = 0; k4 < 4; k4++) {
        float4 f = __ldg((const float4*)&feat[row*16 + k4*4]);
        float4 w = __ldg((const float4*)&wres[c*16 + k4*4]);
        a = fmaf(f.x,w.x,a); a = fmaf(f.y,w.y,a); a = fmaf(f.z,w.z,a); a = fmaf(f.w,w.w,a);
    }
    out[idx] = x + a;
}

extern "C" void kernel_launch(void* const* d_in, const int* in_sizes, int n_in,
                              void* d_out, int out_size)
{
    const float* points   = (const float*)d_in[0];
    const float* nuv      = (const float*)d_in[1];
    const float* features = (const float*)d_in[2];
    const float* w_in1    = (const float*)d_in[3];
    const float* b_in1    = (const float*)d_in[4];
    const float* w_in2    = (const float*)d_in[5];
    const float* b_in2    = (const float*)d_in[6];
    const float* g_in     = (const float*)d_in[7];
    const float* be_in    = (const float*)d_in[8];
    const float* wq       = (const float*)d_in[9];
    const float* bq       = (const float*)d_in[10];
    const float* wk       = (const float*)d_in[11];
    const float* bk       = (const float*)d_in[12];
    const float* wv       = (const float*)d_in[13];
    const float* bv       = (const float*)d_in[14];
    const float* conv_w1  = (const float*)d_in[15];
    const float* conv_b1  = (const float*)d_in[16];
    const float* conv_w2  = (const float*)d_in[17];
    const float* conv_b2  = (const float*)d_in[18];
    const float* rls      = (const float*)d_in[19];
    const float* rbf_a    = (const float*)d_in[20];
    const float* rbf_b    = (const float*)d_in[21];
    const float* rbf_c    = (const float*)d_in[22];
    const float* w_o1     = (const float*)d_in[23];
    const float* b_o1     = (const float*)d_in[24];
    const float* w_o2     = (const float*)d_in[25];
    const float* b_o2     = (const float*)d_in[26];
    const float* g_out    = (const float*)d_in[27];
    const float* be_out   = (const float*)d_in[28];
    const float* w_res    = (const float*)d_in[29];
    const float* b_res    = (const float*)d_in[30];

    k_in_mlp<<<NPTS/4, 256>>>(features, w_in1, b_in1, w_in2, b_in2);
    k_stats_part<<<NPART, 256>>>(0, points, nuv);
    k_stats_comb<<<1, 32>>>(0);
    k_qkv<<<NPTS/4, 256>>>(wq, bq, wk, bk, wv, bv, g_in, be_in);
    k_attn<<<NPTS, 256>>>(points, nuv, conv_w1, conv_b1, conv_w2, conv_b2,
                          rls, rbf_a, rbf_b, rbf_c);
    k_out_mlp<<<NPTS/4, 256>>>(w_o1, b_o1, w_o2, b_o2);
    k_stats_part<<<NPART, 256>>>(1, points, nuv);
    k_stats_comb<<<1, 32>>>(1);
    k_finalize<<<NPTS*64/256, 256>>>(features, g_out, be_out, w_res, b_res, (float*)d_out);
}

// round 10
// speedup vs baseline: 1.2797x; 1.0174x over previous
#include <cuda_runtime.h>
#include <cuda_fp16.h>

#define NPTS 1600
#define HIDC 64
#define TILE 256
#define NPART 25

__device__ float g_h[NPTS*HIDC];     // pre-norm hidden
__device__ float g_Q[NPTS*HIDC];
__device__ uint4 g_KV4[16*NPTS];     // [(head*2+p)*NPTS + j] = {K01,K23,V01,V23} fp16
__device__ float4 g_p4[NPTS];        // {px,py,pz,n0}
__device__ float2 g_n2[NPTS];        // {n1,n2}
__device__ float g_agg[NPTS*HIDC];   // attention output
__device__ float g_o[NPTS*HIDC];     // pre-norm output MLP
__device__ float g_part[NPART*8];    // partial stats
__device__ float g_stats[16];        // [0..3] mu_in [4..7] rs_in [8..11] mu_out [12..15] rs_out

__device__ __forceinline__ float leaky(float x) { return x >= 0.f ? x : 0.2f * x; }

// ---------------- K1: input MLP (pre-norm), smem-staged weights ----------------
__global__ __launch_bounds__(256) void k_in_mlp(
    const float* __restrict__ feat,
    const float* __restrict__ w1, const float* __restrict__ b1,
    const float* __restrict__ w2, const float* __restrict__ b2)
{
    __shared__ float sf[4][16];
    __shared__ float t1[4][68];
    __shared__ float wt[64*65];
    int tid = threadIdx.x;
    int r = tid >> 6, c = tid & 63;
    int row = blockIdx.x*4 + r;

    if (tid < 64) sf[tid >> 4][tid & 15] = feat[blockIdx.x*64 + tid];
#pragma unroll
    for (int i = 0; i < 4; i++) {
        int idx = i*256 + tid;
        int cc = idx >> 4, kk = idx & 15;
        wt[kk*65 + cc] = w1[idx];
    }
    __syncthreads();
    float a = __ldg(&b1[c]);
#pragma unroll
    for (int k = 0; k < 16; k++) a = fmaf(sf[r][k], wt[k*65 + c], a);
    t1[r][c] = leaky(a);
    __syncthreads();
#pragma unroll
    for (int i = 0; i < 16; i++) {
        int idx = i*256 + tid;
        int cc = idx >> 6, kk = idx & 63;
        wt[kk*65 + cc] = w2[idx];
    }
    __syncthreads();
    float a2 = __ldg(&b2[c]);
#pragma unroll
    for (int k = 0; k < 64; k += 4) {
        float4 h4 = *(const float4*)&t1[r][k];
        a2 = fmaf(h4.x, wt[(k  )*65 + c], a2);
        a2 = fmaf(h4.y, wt[(k+1)*65 + c], a2);
        a2 = fmaf(h4.z, wt[(k+2)*65 + c], a2);
        a2 = fmaf(h4.w, wt[(k+3)*65 + c], a2);
    }
    g_h[row*64 + c] = leaky(a2);
}

// ---------------- stats: parallel partial + combine (+ geometry pack on pass 0) ----------------
__global__ __launch_bounds__(256) void k_stats_part(
    int which, const float* __restrict__ points, const float* __restrict__ nuv)
{
    if (which == 0) {
        int p = blockIdx.x*256 + threadIdx.x;
        if (p < NPTS) {
            g_p4[p] = make_float4(points[p*3+0], points[p*3+1], points[p*3+2], nuv[p*9+0]);
            g_n2[p] = make_float2(nuv[p*9+1], nuv[p*9+2]);
        }
    }
    const float4* src = (const float4*)(which ? g_o : g_h);
    float s[4] = {0,0,0,0}, q[4] = {0,0,0,0};
#pragma unroll
    for (int k = 0; k < 4; k++) {
        int idx = blockIdx.x*1024 + k*256 + threadIdx.x;
        float4 v = src[idx];
        int g = (idx & 15) >> 2;
        s[g] += v.x + v.y + v.z + v.w;
        q[g] += v.x*v.x + v.y*v.y + v.z*v.z + v.w*v.w;
    }
    __shared__ float red[256][8];
#pragma unroll
    for (int g = 0; g < 4; g++) { red[threadIdx.x][g] = s[g]; red[threadIdx.x][4+g] = q[g]; }
    __syncthreads();
    for (int st = 128; st > 0; st >>= 1) {
        if (threadIdx.x < st)
#pragma unroll
            for (int k = 0; k < 8; k++) red[threadIdx.x][k] += red[threadIdx.x + st][k];
        __syncthreads();
    }
    if (threadIdx.x < 8) g_part[blockIdx.x*8 + threadIdx.x] = red[0][threadIdx.x];
}

__global__ __launch_bounds__(32) void k_stats_comb(int which)
{
    int off = which ? 8 : 0;
    int g = threadIdx.x;
    if (g < 4) {
        float s = 0.f, q = 0.f;
        for (int b = 0; b < NPART; b++) { s += g_part[b*8 + g]; q += g_part[b*8 + 4 + g]; }
        const float invn = 1.f / (NPTS * 16.f);
        float mu  = s * invn;
        float var = q * invn - mu*mu;
        g_stats[off + g]     = mu;
        g_stats[off + 4 + g] = rsqrtf(var + 1e-5f);
    }
}

// ---------------- K3: normalize + QKV (smem-staged; K,V fp16 packed uint4, transposed) ----------------
__global__ __launch_bounds__(256) void k_qkv(
    const float* __restrict__ wq, const float* __restrict__ bq,
    const float* __restrict__ wk, const float* __restrict__ bk,
    const float* __restrict__ wv, const float* __restrict__ bv,
    const float* __restrict__ gam, const float* __restrict__ bet)
{
    __shared__ float hn[4][68];
    __shared__ float wt[64*65];
    __shared__ float sK[4][64];
    __shared__ float sV[4][64];
    int tid = threadIdx.x;
    int r = tid >> 6, c = tid & 63;
    int row = blockIdx.x*4 + r;

    {
        int g = c >> 4;
        float x = g_h[row*64 + c];
        float v = (x - g_stats[g]) * g_stats[4+g];
        hn[r][c] = fmaf(v, __ldg(&gam[c]), __ldg(&bet[c]));
    }

    const float* Ws[3] = {wq, wk, wv};
    const float* Bs[3] = {bq, bk, bv};
#pragma unroll
    for (int mtx = 0; mtx < 3; mtx++) {
        __syncthreads();
#pragma unroll
        for (int i = 0; i < 16; i++) {
            int idx = i*256 + tid;
            int cc = idx >> 6, kk = idx & 63;
            wt[kk*65 + cc] = Ws[mtx][idx];
        }
        __syncthreads();
        float a = __ldg(&Bs[mtx][c]);
#pragma unroll
        for (int k = 0; k < 64; k += 4) {
            float4 h4 = *(const float4*)&hn[r][k];
            a = fmaf(h4.x, wt[(k  )*65 + c], a);
            a = fmaf(h4.y, wt[(k+1)*65 + c], a);
            a = fmaf(h4.z, wt[(k+2)*65 + c], a);
            a = fmaf(h4.w, wt[(k+3)*65 + c], a);
        }
        if (mtx == 0)      g_Q[row*64 + c] = a;
        else if (mtx == 1) sK[r][c] = a;
        else               sV[r][c] = a;
    }
    __syncthreads();
    // pack: 64 threads = 4 rows x 16 quad-groups; g_KV4[g4*NPTS + row] = {K01,K23,V01,V23}
    if (tid < 64) {
        int rr = tid >> 4, g4 = tid & 15;
        int rw = blockIdx.x*4 + rr;
        __half2 k01 = __floats2half2_rn(sK[rr][4*g4+0], sK[rr][4*g4+1]);
        __half2 k23 = __floats2half2_rn(sK[rr][4*g4+2], sK[rr][4*g4+3]);
        __half2 v01 = __floats2half2_rn(sV[rr][4*g4+0], sV[rr][4*g4+1]);
        __half2 v23 = __floats2half2_rn(sV[rr][4*g4+2], sV[rr][4*g4+3]);
        uint4 u;
        u.x = *(unsigned int*)&k01; u.y = *(unsigned int*)&k23;
        u.z = *(unsigned int*)&v01; u.w = *(unsigned int*)&v23;
        g_KV4[g4*NPTS + rw] = u;
    }
}

// ---------------- K4: fused pairwise geometry + conv + attention (pipelined) ----------------
__device__ __forceinline__ void attn_body(
    int j, const uint4 fu, const float wgt, const uint4* __restrict__ KVb,
    const __half2* qh2, const __half2* w2h, const __half2* b2h,
    float* acc, float& denom)
{
    uint4 u0 = __ldg(&KVb[j]);
    uint4 u1 = __ldg(&KVb[NPTS + j]);
    __half2 t0 = __hmul2(qh2[0], *(const __half2*)&u0.x);
    t0 = __hfma2(qh2[1], *(const __half2*)&u0.y, t0);
    __half2 t1 = __hmul2(qh2[2], *(const __half2*)&u1.x);
    t1 = __hfma2(qh2[3], *(const __half2*)&u1.y, t1);
    float2 sf = __half22float2(__hadd2(t0, t1));
    float e = __expf(sf.x + sf.y);
    denom += e;
    float ew = e * wgt;

    __half2 h01 = *(const __half2*)&fu.x, h23 = *(const __half2*)&fu.y;
    __half2 h45 = *(const __half2*)&fu.z, h67 = *(const __half2*)&fu.w;
    __half2 fb8[8];
    fb8[0] = __low2half2(h01); fb8[1] = __high2half2(h01);
    fb8[2] = __low2half2(h23); fb8[3] = __high2half2(h23);
    fb8[4] = __low2half2(h45); fb8[5] = __high2half2(h45);
    fb8[6] = __low2half2(h67); fb8[7] = __high2half2(h67);
    __half2 a0 = b2h[0], a1 = b2h[1], a2 = b2h[2], a3 = b2h[3];
#pragma unroll
    for (int k = 0; k < 8; k++) {
        a0 = __hfma2(fb8[k], w2h[k],    a0);
        a1 = __hfma2(fb8[k], w2h[8+k],  a1);
        a2 = __hfma2(fb8[k], w2h[16+k], a2);
        a3 = __hfma2(fb8[k], w2h[24+k], a3);
    }
    const __half2 zero2 = __float2half2_rn(0.f);
    a0 = __hmax2(a0, zero2); a1 = __hmax2(a1, zero2);
    a2 = __hmax2(a2, zero2); a3 = __hmax2(a3, zero2);
    {
        float2 p = __half22float2(__hmul2(a0, *(const __half2*)&u0.z));
        acc[0] = fmaf(ew, p.x, acc[0]); acc[1] = fmaf(ew, p.y, acc[1]);
    }
    {
        float2 p = __half22float2(__hmul2(a1, *(const __half2*)&u0.w));
        acc[2] = fmaf(ew, p.x, acc[2]); acc[3] = fmaf(ew, p.y, acc[3]);
    }
    {
        float2 p = __half22float2(__hmul2(a2, *(const __half2*)&u1.z));
        acc[4] = fmaf(ew, p.x, acc[4]); acc[5] = fmaf(ew, p.y, acc[5]);
    }
    {
        float2 p = __half22float2(__hmul2(a3, *(const __half2*)&u1.w));
        acc[6] = fmaf(ew, p.x, acc[6]); acc[7] = fmaf(ew, p.y, acc[7]);
    }
}

// stage-1: geometry + RBF + conv1 for point j (inputs preloaded), write packed F1 + W
__device__ __forceinline__ void stage1_compute(
    const float4 pj, const float2 nj,
    const float* sPi, const float* sNuv,
    const float* sw1, const float* sb1,
    const float* sra, const float* srb, const float* src, float inv2s2,
    uint4* outF, float* outW)
{
    const float INVS = 0.11785113019775793f;   // 1/(sqrt(2)*6)
    float dx = (pj.x - sPi[0]) * INVS;
    float dy = (pj.y - sPi[1]) * INVS;
    float dz = (pj.z - sPi[2]) * INVS;
    float ndot = sNuv[0]*pj.w + sNuv[1]*nj.x + sNuv[2]*nj.y;
    float u = 2.f - ndot;
    float d2 = (dx*dx + dy*dy + dz*dz) * u * u;
    float t = 1.f / (1.f + d2 * (1.f/3.f));
    *outW = t*t*t;
    float bd = sqrtf(d2);
    float X[8];
    X[0] = sNuv[0]*dx + sNuv[1]*dy + sNuv[2]*dz;
    X[1] = sNuv[3]*dx + sNuv[4]*dy + sNuv[5]*dz;
    X[2] = sNuv[6]*dx + sNuv[7]*dy + sNuv[8]*dz;
    X[3] = ndot;
    float rp0 = srb[0], rp1 = srb[1], rp2 = srb[2], rp3 = srb[3];
#pragma unroll
    for (int r = 0; r < 8; r++) {
        float dd = bd - src[r];
        float e = __expf(-dd*dd * inv2s2);
        rp0 = fmaf(e, sra[0*8+r], rp0);
        rp1 = fmaf(e, sra[1*8+r], rp1);
        rp2 = fmaf(e, sra[2*8+r], rp2);
        rp3 = fmaf(e, sra[3*8+r], rp3);
    }
    X[4] = rp0; X[5] = rp1; X[6] = rp2; X[7] = rp3;
    float F[8];
#pragma unroll
    for (int c = 0; c < 8; c++) {
        float a = sb1[c];
#pragma unroll
        for (int k = 0; k < 8; k++) a = fmaf(X[k], sw1[c*8+k], a);
        F[c] = fmaxf(a, 0.f);
    }
    uint4 pkv;
    __half2 h01 = __floats2half2_rn(F[0], F[1]);
    __half2 h23 = __floats2half2_rn(F[2], F[3]);
    __half2 h45 = __floats2half2_rn(F[4], F[5]);
    __half2 h67 = __floats2half2_rn(F[6], F[7]);
    pkv.x = *(unsigned int*)&h01; pkv.y = *(unsigned int*)&h23;
    pkv.z = *(unsigned int*)&h45; pkv.w = *(unsigned int*)&h67;
    *outF = pkv;
}

__global__ __launch_bounds__(256, 2) void k_attn(
    const float* __restrict__ points, const float* __restrict__ nuv,
    const float* __restrict__ cw1, const float* __restrict__ cb1,
    const float* __restrict__ cw2, const float* __restrict__ cb2,
    const float* __restrict__ rls, const float* __restrict__ ra,
    const float* __restrict__ rb, const float* __restrict__ rc)
{
    const float SCALE = 0.3535533905932738f;    // 1/sqrt(8)
    int i = blockIdx.x;
    int tid = threadIdx.x, warp = tid >> 5, lane = tid & 31;

    __shared__ uint4 sF1h[2][TILE];
    __shared__ float sWgt[2][TILE];
    __shared__ float sQ[64];
    __shared__ float sNuv[9], sPi[3];
    __shared__ float sw1[64], sb1[8], sra[32], srb[4], src[8], sInv2s2;

    if (tid < 64) { sw1[tid] = __ldg(&cw1[tid]); sQ[tid] = g_Q[i*64 + tid]; }
    if (tid < 8)  { sb1[tid] = __ldg(&cb1[tid]); src[tid] = __ldg(&rc[tid]); }
    if (tid < 32) sra[tid] = __ldg(&ra[tid]);
    if (tid < 4)  srb[tid] = __ldg(&rb[tid]);
    if (tid < 9)  sNuv[tid] = nuv[i*9 + tid];
    if (tid < 3)  sPi[tid]  = points[i*3 + tid];
    if (tid == 0) { float sg = fmaxf(__expf(__ldg(&rls[0])), 1e-6f); sInv2s2 = 0.5f/(sg*sg); }
    __syncthreads();

    // head-private: conv_w2 half2 c-pair packed, bias, Q half2 with scale folded
    __half2 w2h[32], b2h[4], qh2[4];
#pragma unroll
    for (int cp = 0; cp < 4; cp++) {
        b2h[cp] = __floats2half2_rn(__ldg(&cb2[warp*8 + 2*cp]), __ldg(&cb2[warp*8 + 2*cp + 1]));
        qh2[cp] = __floats2half2_rn(sQ[warp*8 + 2*cp] * SCALE, sQ[warp*8 + 2*cp + 1] * SCALE);
#pragma unroll
        for (int k = 0; k < 8; k++)
            w2h[cp*8 + k] = __floats2half2_rn(__ldg(&cw2[(warp*8 + 2*cp)*8 + k]),
                                              __ldg(&cw2[(warp*8 + 2*cp + 1)*8 + k]));
    }
    float denom = 0.f;
    float acc[8];
#pragma unroll
    for (int c = 0; c < 8; c++) acc[c] = 0.f;

    const uint4* KVb = &g_KV4[warp*2*NPTS];

    // prologue: stage-1 for tile 0 (tid < 256 <= NPTS always valid)
    {
        float4 pj = __ldg(&g_p4[tid]);
        float2 nj = __ldg(&g_n2[tid]);
        stage1_compute(pj, nj, sPi, sNuv, sw1, sb1, sra, srb, src, sInv2s2,
                       &sF1h[0][tid], &sWgt[0][tid]);
    }
    __syncthreads();

    int p = 0;
    for (int tb = 0; tb < NPTS; tb += TILE) {
        // prefetch next tile's geometry into registers
        int jn = tb + TILE + tid;
        bool pre = (jn < NPTS);
        float4 pj; float2 nj;
        if (pre) { pj = __ldg(&g_p4[jn]); nj = __ldg(&g_n2[jn]); }

        // stage 2: consume current buffer
        int cnt = min(TILE, NPTS - tb);
        if (cnt == TILE) {
#pragma unroll 4
            for (int it = 0; it < TILE/32; it++) {
                int jj = it*32 + lane;
                attn_body(tb + jj, sF1h[p][jj], sWgt[p][jj], KVb, qh2, w2h, b2h, acc, denom);
            }
        } else {
#pragma unroll 2
            for (int it = 0; it < 2; it++) {
                int jj = it*32 + lane;
                if (jj < cnt)
                    attn_body(tb + jj, sF1h[p][jj], sWgt[p][jj], KVb, qh2, w2h, b2h, acc, denom);
            }
        }

        // stage 1: produce next buffer
        if (pre)
            stage1_compute(pj, nj, sPi, sNuv, sw1, sb1, sra, srb, src, sInv2s2,
                           &sF1h[p^1][tid], &sWgt[p^1][tid]);
        __syncthreads();
        p ^= 1;
    }

    // warp reductions
#pragma unroll
    for (int o = 16; o > 0; o >>= 1) denom += __shfl_xor_sync(0xffffffffu, denom, o);
#pragma unroll
    for (int c = 0; c < 8; c++)
#pragma unroll
        for (int o = 16; o > 0; o >>= 1) acc[c] += __shfl_xor_sync(0xffffffffu, acc[c], o);
    if (lane == 0) {
        float inv = 1.f / denom;
#pragma unroll
        for (int c = 0; c < 8; c++) g_agg[i*64 + warp*8 + c] = acc[c] * inv;
    }
}

// ---------------- K5: output MLP (pre-norm), smem-staged ----------------
__global__ __launch_bounds__(256) void k_out_mlp(
    const float* __restrict__ w1, const float* __restrict__ b1,
    const float* __restrict__ w2, const float* __restrict__ b2)
{
    __shared__ float a0[4][68];
    __shared__ float t1[4][68];
    __shared__ float wt[64*65];
    int tid = threadIdx.x;
    int r = tid >> 6, c = tid & 63;
    int row = blockIdx.x*4 + r;

    a0[r][c] = g_agg[row*64 + c];
#pragma unroll
    for (int i = 0; i < 16; i++) {
        int idx = i*256 + tid;
        int cc = idx >> 6, kk = idx & 63;
        wt[kk*65 + cc] = w1[idx];
    }
    __syncthreads();
    float a = __ldg(&b1[c]);
#pragma unroll
    for (int k = 0; k < 64; k += 4) {
        float4 h4 = *(const float4*)&a0[r][k];
        a = fmaf(h4.x, wt[(k  )*65 + c], a);
        a = fmaf(h4.y, wt[(k+1)*65 + c], a);
        a = fmaf(h4.z, wt[(k+2)*65 + c], a);
        a = fmaf(h4.w, wt[(k+3)*65 + c], a);
    }
    t1[r][c] = leaky(a);
    __syncthreads();
#pragma unroll
    for (int i = 0; i < 16; i++) {
        int idx = i*256 + tid;
        int cc = idx >> 6, kk = idx & 63;
        wt[kk*65 + cc] = w2[idx];
    }
    __syncthreads();
    float a2 = __ldg(&b2[c]);
#pragma unroll
    for (int k = 0; k < 64; k += 4) {
        float4 h4 = *(const float4*)&t1[r][k];
        a2 = fmaf(h4.x, wt[(k  )*65 + c], a2);
        a2 = fmaf(h4.y, wt[(k+1)*65 + c], a2);
        a2 = fmaf(h4.z, wt[(k+2)*65 + c], a2);
        a2 = fmaf(h4.w, wt[(k+3)*65 + c], a2);
    }
    g_o[row*64 + c] = leaky(a2);
}

// ---------------- K7: final norm + residual ----------------
__global__ __launch_bounds__(256) void k_finalize(
    const float* __restrict__ feat,
    const float* __restrict__ gam, const float* __restrict__ bet,
    const float* __restrict__ wres, const float* __restrict__ bres,
    float* __restrict__ out)
{
    int idx = blockIdx.x * 256 + threadIdx.x;
    int row = idx >> 6, c = idx & 63, g = c >> 4;
    float x = (g_o[idx] - g_stats[8+g]) * g_stats[12+g];
    x = fmaf(x, __ldg(&gam[c]), __ldg(&bet[c]));
    float a = __ldg(&bres[c]);
#pragma unroll
    for (int k4 = 0; k4 < 4; k4++) {
        float4 f = __ldg((const float4*)&feat[row*16 + k4*4]);
        float4 w = __ldg((const float4*)&wres[c*16 + k4*4]);
        a = fmaf(f.x,w.x,a); a = fmaf(f.y,w.y,a); a = fmaf(f.z,w.z,a); a = fmaf(f.w,w.w,a);
    }
    out[idx] = x + a;
}

extern "C" void kernel_launch(void* const* d_in, const int* in_sizes, int n_in,
                              void* d_out, int out_size)
{
    const float* points   = (const float*)d_in[0];
    const float* nuv      = (const float*)d_in[1];
    const float* features = (const float*)d_in[2];
    const float* w_in1    = (const float*)d_in[3];
    const float* b_in1    = (const float*)d_in[4];
    const float* w_in2    = (const float*)d_in[5];
    const float* b_in2    = (const float*)d_in[6];
    const float* g_in     = (const float*)d_in[7];
    const float* be_in    = (const float*)d_in[8];
    const float* wq       = (const float*)d_in[9];
    const float* bq       = (const float*)d_in[10];
    const float* wk       = (const float*)d_in[11];
    const float* bk       = (const float*)d_in[12];
    const float* wv       = (const float*)d_in[13];
    const float* bv       = (const float*)d_in[14];
    const float* conv_w1  = (const float*)d_in[15];
    const float* conv_b1  = (const float*)d_in[16];
    const float* conv_w2  = (const float*)d_in[17];
    const float* conv_b2  = (const float*)d_in[18];
    const float* rls      = (const float*)d_in[19];
    const float* rbf_a    = (const float*)d_in[20];
    const float* rbf_b    = (const float*)d_in[21];
    const float* rbf_c    = (const float*)d_in[22];
    const float* w_o1     = (const float*)d_in[23];
    const float* b_o1     = (const float*)d_in[24];
    const float* w_o2     = (const float*)d_in[25];
    const float* b_o2     = (const float*)d_in[26];
    const float* g_out    = (const float*)d_in[27];
    const float* be_out   = (const float*)d_in[28];
    const float* w_res    = (const float*)d_in[29];
    const float* b_res    = (const float*)d_in[30];

    k_in_mlp<<<NPTS/4, 256>>>(features, w_in1, b_in1, w_in2, b_in2);
    k_stats_part<<<NPART, 256>>>(0, points, nuv);
    k_stats_comb<<<1, 32>>>(0);
    k_qkv<<<NPTS/4, 256>>>(wq, bq, wk, bk, wv, bv, g_in, be_in);
    k_attn<<<NPTS, 256>>>(points, nuv, conv_w1, conv_b1, conv_w2, conv_b2,
                          rls, rbf_a, rbf_b, rbf_c);
    k_out_mlp<<<NPTS/4, 256>>>(w_o1, b_o1, w_o2, b_o2);
    k_stats_part<<<NPART, 256>>>(1, points, nuv);
    k_stats_comb<<<1, 32>>>(1);
    k_finalize<<<NPTS*64/256, 256>>>(features, g_out, be_out, w_res, b_res, (float*)d_out);
}

// round 11
// speedup vs baseline: 1.3556x; 1.0593x over previous
#include <cuda_runtime.h>
#include <cuda_fp16.h>

#define NPTS 1600
#define HIDC 64
#define TILE 256
#define NPART 25

__device__ float g_h[NPTS*HIDC];     // pre-norm hidden
__device__ float g_Q[NPTS*HIDC];
__device__ uint4 g_K4h[8*NPTS];      // [h*NPTS + j] = 8 halves of K (head-row)
__device__ uint4 g_V4h[8*NPTS];      // [h*NPTS + j] = 8 halves of V (head-row)
__device__ float4 g_p4[NPTS];        // {px,py,pz,n0}
__device__ float2 g_n2[NPTS];        // {n1,n2}
__device__ float g_agg[NPTS*HIDC];   // attention output
__device__ float g_o[NPTS*HIDC];     // pre-norm output MLP
__device__ float g_part[NPART*8];    // partial stats

__device__ __forceinline__ float leaky(float x) { return x >= 0.f ? x : 0.2f * x; }

// ---------------- K1: input MLP (pre-norm), smem-staged weights ----------------
__global__ __launch_bounds__(256) void k_in_mlp(
    const float* __restrict__ feat,
    const float* __restrict__ w1, const float* __restrict__ b1,
    const float* __restrict__ w2, const float* __restrict__ b2)
{
    __shared__ float sf[4][16];
    __shared__ float t1[4][68];
    __shared__ float wt[64*65];
    int tid = threadIdx.x;
    int r = tid >> 6, c = tid & 63;
    int row = blockIdx.x*4 + r;

    if (tid < 64) sf[tid >> 4][tid & 15] = feat[blockIdx.x*64 + tid];
#pragma unroll
    for (int i = 0; i < 4; i++) {
        int idx = i*256 + tid;
        int cc = idx >> 4, kk = idx & 15;
        wt[kk*65 + cc] = w1[idx];
    }
    __syncthreads();
    float a = __ldg(&b1[c]);
#pragma unroll
    for (int k = 0; k < 16; k++) a = fmaf(sf[r][k], wt[k*65 + c], a);
    t1[r][c] = leaky(a);
    __syncthreads();
#pragma unroll
    for (int i = 0; i < 16; i++) {
        int idx = i*256 + tid;
        int cc = idx >> 6, kk = idx & 63;
        wt[kk*65 + cc] = w2[idx];
    }
    __syncthreads();
    float a2 = __ldg(&b2[c]);
#pragma unroll
    for (int k = 0; k < 64; k += 4) {
        float4 h4 = *(const float4*)&t1[r][k];
        a2 = fmaf(h4.x, wt[(k  )*65 + c], a2);
        a2 = fmaf(h4.y, wt[(k+1)*65 + c], a2);
        a2 = fmaf(h4.z, wt[(k+2)*65 + c], a2);
        a2 = fmaf(h4.w, wt[(k+3)*65 + c], a2);
    }
    g_h[row*64 + c] = leaky(a2);
}

// ---------------- stats: parallel partial (+ geometry pack on pass 0) ----------------
__global__ __launch_bounds__(256) void k_stats_part(
    int which, const float* __restrict__ points, const float* __restrict__ nuv)
{
    if (which == 0) {
        int p = blockIdx.x*256 + threadIdx.x;
        if (p < NPTS) {
            g_p4[p] = make_float4(points[p*3+0], points[p*3+1], points[p*3+2], nuv[p*9+0]);
            g_n2[p] = make_float2(nuv[p*9+1], nuv[p*9+2]);
        }
    }
    const float4* src = (const float4*)(which ? g_o : g_h);
    float s[4] = {0,0,0,0}, q[4] = {0,0,0,0};
#pragma unroll
    for (int k = 0; k < 4; k++) {
        int idx = blockIdx.x*1024 + k*256 + threadIdx.x;
        float4 v = src[idx];
        int g = (idx & 15) >> 2;
        s[g] += v.x + v.y + v.z + v.w;
        q[g] += v.x*v.x + v.y*v.y + v.z*v.z + v.w*v.w;
    }
    __shared__ float red[256][8];
#pragma unroll
    for (int g = 0; g < 4; g++) { red[threadIdx.x][g] = s[g]; red[threadIdx.x][4+g] = q[g]; }
    __syncthreads();
    for (int st = 128; st > 0; st >>= 1) {
        if (threadIdx.x < st)
#pragma unroll
            for (int k = 0; k < 8; k++) red[threadIdx.x][k] += red[threadIdx.x + st][k];
        __syncthreads();
    }
    if (threadIdx.x < 8) g_part[blockIdx.x*8 + threadIdx.x] = red[0][threadIdx.x];
}

// combine partials for group g -> mu, rs
__device__ __forceinline__ void stats_combine(int g, float& mu, float& rs)
{
    float s = 0.f, q = 0.f;
#pragma unroll
    for (int b = 0; b < NPART; b++) { s += g_part[b*8 + g]; q += g_part[b*8 + 4 + g]; }
    const float invn = 1.f / (NPTS * 16.f);
    mu = s * invn;
    float var = q * invn - mu*mu;
    rs = rsqrtf(var + 1e-5f);
}

// ---------------- K3: normalize + QKV (smem-staged; K,V fp16 head-row packed) ----------------
__global__ __launch_bounds__(256) void k_qkv(
    const float* __restrict__ wq, const float* __restrict__ bq,
    const float* __restrict__ wk, const float* __restrict__ bk,
    const float* __restrict__ wv, const float* __restrict__ bv,
    const float* __restrict__ gam, const float* __restrict__ bet)
{
    __shared__ float hn[4][68];
    __shared__ float wt[64*65];
    __shared__ float sK[4][64];
    __shared__ float sV[4][64];
    int tid = threadIdx.x;
    int r = tid >> 6, c = tid & 63;
    int row = blockIdx.x*4 + r;

    {
        float mu, rs;
        stats_combine(c >> 4, mu, rs);
        float x = g_h[row*64 + c];
        float v = (x - mu) * rs;
        hn[r][c] = fmaf(v, __ldg(&gam[c]), __ldg(&bet[c]));
    }

    const float* Ws[3] = {wq, wk, wv};
    const float* Bs[3] = {bq, bk, bv};
#pragma unroll
    for (int mtx = 0; mtx < 3; mtx++) {
        __syncthreads();
#pragma unroll
        for (int i = 0; i < 16; i++) {
            int idx = i*256 + tid;
            int cc = idx >> 6, kk = idx & 63;
            wt[kk*65 + cc] = Ws[mtx][idx];
        }
        __syncthreads();
        float a = __ldg(&Bs[mtx][c]);
#pragma unroll
        for (int k = 0; k < 64; k += 4) {
            float4 h4 = *(const float4*)&hn[r][k];
            a = fmaf(h4.x, wt[(k  )*65 + c], a);
            a = fmaf(h4.y, wt[(k+1)*65 + c], a);
            a = fmaf(h4.z, wt[(k+2)*65 + c], a);
            a = fmaf(h4.w, wt[(k+3)*65 + c], a);
        }
        if (mtx == 0)      g_Q[row*64 + c] = a;
        else if (mtx == 1) sK[r][c] = a;
        else               sV[r][c] = a;
    }
    __syncthreads();
    // pack head-row fp16: 128 threads = 4 rows x 8 heads x 4 uints
    if (tid < 128) {
        int rr = tid >> 5, hh = (tid >> 2) & 7, t = tid & 3;
        int rw = blockIdx.x*4 + rr;
        __half2 kh = __floats2half2_rn(sK[rr][hh*8 + 2*t], sK[rr][hh*8 + 2*t + 1]);
        __half2 vh = __floats2half2_rn(sV[rr][hh*8 + 2*t], sV[rr][hh*8 + 2*t + 1]);
        ((unsigned int*)g_K4h)[(hh*NPTS + rw)*4 + t] = *(unsigned int*)&kh;
        ((unsigned int*)g_V4h)[(hh*NPTS + rw)*4 + t] = *(unsigned int*)&vh;
    }
}

// ---------------- K4: fused pairwise geometry + conv + attention (pipelined, HMMA conv) ----------------
// stage-1: geometry + RBF + conv1 for point j (inputs preloaded), write packed F1 + W
__device__ __forceinline__ void stage1_compute(
    const float4 pj, const float2 nj,
    const float* sPi, const float* sNuv,
    const float* sw1, const float* sb1,
    const float* sra, const float* srb, const float* src, float inv2s2,
    uint4* outF, float* outW)
{
    const float INVS = 0.11785113019775793f;   // 1/(sqrt(2)*6)
    float dx = (pj.x - sPi[0]) * INVS;
    float dy = (pj.y - sPi[1]) * INVS;
    float dz = (pj.z - sPi[2]) * INVS;
    float ndot = sNuv[0]*pj.w + sNuv[1]*nj.x + sNuv[2]*nj.y;
    float u = 2.f - ndot;
    float d2 = (dx*dx + dy*dy + dz*dz) * u * u;
    float t = 1.f / (1.f + d2 * (1.f/3.f));
    *outW = t*t*t;
    float bd = sqrtf(d2);
    float X[8];
    X[0] = sNuv[0]*dx + sNuv[1]*dy + sNuv[2]*dz;
    X[1] = sNuv[3]*dx + sNuv[4]*dy + sNuv[5]*dz;
    X[2] = sNuv[6]*dx + sNuv[7]*dy + sNuv[8]*dz;
    X[3] = ndot;
    float rp0 = srb[0], rp1 = srb[1], rp2 = srb[2], rp3 = srb[3];
#pragma unroll
    for (int r = 0; r < 8; r++) {
        float dd = bd - src[r];
        float e = __expf(-dd*dd * inv2s2);
        rp0 = fmaf(e, sra[0*8+r], rp0);
        rp1 = fmaf(e, sra[1*8+r], rp1);
        rp2 = fmaf(e, sra[2*8+r], rp2);
        rp3 = fmaf(e, sra[3*8+r], rp3);
    }
    X[4] = rp0; X[5] = rp1; X[6] = rp2; X[7] = rp3;
    float F[8];
#pragma unroll
    for (int c = 0; c < 8; c++) {
        float a = sb1[c];
#pragma unroll
        for (int k = 0; k < 8; k++) a = fmaf(X[k], sw1[c*8+k], a);
        F[c] = fmaxf(a, 0.f);
    }
    uint4 pkv;
    __half2 h01 = __floats2half2_rn(F[0], F[1]);
    __half2 h23 = __floats2half2_rn(F[2], F[3]);
    __half2 h45 = __floats2half2_rn(F[4], F[5]);
    __half2 h67 = __floats2half2_rn(F[6], F[7]);
    pkv.x = *(unsigned int*)&h01; pkv.y = *(unsigned int*)&h23;
    pkv.z = *(unsigned int*)&h45; pkv.w = *(unsigned int*)&h67;
    *outF = pkv;
}

__device__ __forceinline__ void mma16n8k8(
    float& d0, float& d1, float& d2, float& d3,
    unsigned int a0, unsigned int a1, unsigned int b0,
    float c0, float c1, float c2, float c3)
{
    asm volatile(
        "mma.sync.aligned.m16n8k8.row.col.f32.f16.f16.f32 "
        "{%0,%1,%2,%3}, {%4,%5}, {%6}, {%7,%8,%9,%10};"
        : "=f"(d0), "=f"(d1), "=f"(d2), "=f"(d3)
        : "r"(a0), "r"(a1), "r"(b0),
          "f"(c0), "f"(c1), "f"(c2), "f"(c3));
}

__global__ __launch_bounds__(256, 2) void k_attn(
    const float* __restrict__ points, const float* __restrict__ nuv,
    const float* __restrict__ cw1, const float* __restrict__ cb1,
    const float* __restrict__ cw2, const float* __restrict__ cb2,
    const float* __restrict__ rls, const float* __restrict__ ra,
    const float* __restrict__ rb, const float* __restrict__ rc)
{
    const float SCALE = 0.3535533905932738f;    // 1/sqrt(8)
    int i = blockIdx.x;
    int tid = threadIdx.x, warp = tid >> 5, lane = tid & 31;
    int g = lane >> 2, t = lane & 3;

    __shared__ uint4 sF1h[2][TILE];
    __shared__ float sWgt[2][TILE];
    __shared__ float sQ[64];
    __shared__ float sNuv[9], sPi[3];
    __shared__ float sw1[64], sb1[8], sra[32], srb[4], src[8], sInv2s2;

    if (tid < 64) { sw1[tid] = __ldg(&cw1[tid]); sQ[tid] = g_Q[i*64 + tid]; }
    if (tid < 8)  { sb1[tid] = __ldg(&cb1[tid]); src[tid] = __ldg(&rc[tid]); }
    if (tid < 32) sra[tid] = __ldg(&ra[tid]);
    if (tid < 4)  srb[tid] = __ldg(&rb[tid]);
    if (tid < 9)  sNuv[tid] = nuv[i*9 + tid];
    if (tid < 3)  sPi[tid]  = points[i*3 + tid];
    if (tid == 0) { float sg = fmaxf(__expf(__ldg(&rls[0])), 1e-6f); sInv2s2 = 0.5f/(sg*sg); }
    __syncthreads();

    // B fragment: b0 = {W2[c=g][k=2t], W2[g][2t+1]} for this head; bias in C operand
    unsigned int bfrag;
    {
        __half2 hb = __floats2half2_rn(__ldg(&cw2[(warp*8 + g)*8 + 2*t]),
                                       __ldg(&cw2[(warp*8 + g)*8 + 2*t + 1]));
        bfrag = *(unsigned int*)&hb;
    }
    float bias0 = __ldg(&cb2[warp*8 + 2*t]);
    float bias1 = __ldg(&cb2[warp*8 + 2*t + 1]);

    // Q half2 with scale folded
    __half2 qh2[4];
#pragma unroll
    for (int cp = 0; cp < 4; cp++)
        qh2[cp] = __floats2half2_rn(sQ[warp*8 + 2*cp] * SCALE, sQ[warp*8 + 2*cp + 1] * SCALE);

    float denom = 0.f;
    float acc0 = 0.f, acc1 = 0.f;   // partial sums for c = 2t, 2t+1

    const uint4* Kb = &g_K4h[warp*NPTS];
    const unsigned int* Vu = (const unsigned int*)&g_V4h[warp*NPTS];

    // prologue: stage-1 for tile 0
    {
        float4 pj = __ldg(&g_p4[tid]);
        float2 nj = __ldg(&g_n2[tid]);
        stage1_compute(pj, nj, sPi, sNuv, sw1, sb1, sra, srb, src, sInv2s2,
                       &sF1h[0][tid], &sWgt[0][tid]);
    }
    __syncthreads();

    int p = 0;
    for (int tb = 0; tb < NPTS; tb += TILE) {
        // prefetch next tile's geometry into registers
        int jn = tb + TILE + tid;
        bool pre = (jn < NPTS);
        float4 pj; float2 nj;
        if (pre) { pj = __ldg(&g_p4[jn]); nj = __ldg(&g_n2[jn]); }

        int ng = min(TILE, NPTS - tb) >> 5;   // groups of 32 (always exact: 8 or 2)
#pragma unroll 2
        for (int it = 0; it < ng; it++) {
            int sbase = it*32;
            int jb = tb + sbase;
            // --- e-phase: lane = j ---
            uint4 ku = __ldg(&Kb[jb + lane]);
            __half2 s0 = __hmul2(qh2[0], *(const __half2*)&ku.x);
            s0 = __hfma2(qh2[1], *(const __half2*)&ku.y, s0);
            __half2 s1 = __hmul2(qh2[2], *(const __half2*)&ku.z);
            s1 = __hfma2(qh2[3], *(const __half2*)&ku.w, s1);
            float2 sf = __half22float2(__hadd2(s0, s1));
            float e = __expf(sf.x + sf.y);
            denom += e;
            float ew = e * sWgt[p][sbase + lane];

            // --- fragment phase: Fh^T[32j x 8c] via 2x HMMA ---
            const unsigned int* F1u = (const unsigned int*)&sF1h[p][sbase];
            unsigned int a0 = F1u[(g     )*4 + t];
            unsigned int a1 = F1u[(g +  8)*4 + t];
            unsigned int a2 = F1u[(g + 16)*4 + t];
            unsigned int a3 = F1u[(g + 24)*4 + t];
            float ew0 = __shfl_sync(0xffffffffu, ew, g);
            float ew1 = __shfl_sync(0xffffffffu, ew, g + 8);
            float ew2 = __shfl_sync(0xffffffffu, ew, g + 16);
            float ew3 = __shfl_sync(0xffffffffu, ew, g + 24);

            float d0, d1, d2, d3;
            mma16n8k8(d0, d1, d2, d3, a0, a1, bfrag, bias0, bias1, bias0, bias1);
            {
                unsigned int v0 = __ldg(&Vu[(jb + g     )*4 + t]);
                unsigned int v1 = __ldg(&Vu[(jb + 8 + g )*4 + t]);
                float2 vf0 = __half22float2(*(const __half2*)&v0);
                float2 vf1 = __half22float2(*(const __half2*)&v1);
                acc0 = fmaf(ew0 * fmaxf(d0, 0.f), vf0.x, acc0);
                acc1 = fmaf(ew0 * fmaxf(d1, 0.f), vf0.y, acc1);
                acc0 = fmaf(ew1 * fmaxf(d2, 0.f), vf1.x, acc0);
                acc1 = fmaf(ew1 * fmaxf(d3, 0.f), vf1.y, acc1);
            }
            mma16n8k8(d0, d1, d2, d3, a2, a3, bfrag, bias0, bias1, bias0, bias1);
            {
                unsigned int v2 = __ldg(&Vu[(jb + 16 + g)*4 + t]);
                unsigned int v3 = __ldg(&Vu[(jb + 24 + g)*4 + t]);
                float2 vf2 = __half22float2(*(const __half2*)&v2);
                float2 vf3 = __half22float2(*(const __half2*)&v3);
                acc0 = fmaf(ew2 * fmaxf(d0, 0.f), vf2.x, acc0);
                acc1 = fmaf(ew2 * fmaxf(d1, 0.f), vf2.y, acc1);
                acc0 = fmaf(ew3 * fmaxf(d2, 0.f), vf3.x, acc0);
                acc1 = fmaf(ew3 * fmaxf(d3, 0.f), vf3.y, acc1);
            }
        }

        // stage 1: produce next buffer
        if (pre)
            stage1_compute(pj, nj, sPi, sNuv, sw1, sb1, sra, srb, src, sInv2s2,
                           &sF1h[p^1][tid], &sWgt[p^1][tid]);
        __syncthreads();
        p ^= 1;
    }

    // reductions: denom over full warp; acc over lanes sharing t (stride-4 classes)
#pragma unroll
    for (int o = 16; o > 0; o >>= 1) denom += __shfl_xor_sync(0xffffffffu, denom, o);
#pragma unroll
    for (int o = 4; o <= 16; o <<= 1) {
        acc0 += __shfl_xor_sync(0xffffffffu, acc0, o);
        acc1 += __shfl_xor_sync(0xffffffffu, acc1, o);
    }
    if (lane < 4) {
        float inv = 1.f / denom;
        g_agg[i*64 + warp*8 + 2*lane]     = acc0 * inv;
        g_agg[i*64 + warp*8 + 2*lane + 1] = acc1 * inv;
    }
}

// ---------------- K5: output MLP (pre-norm), smem-staged ----------------
__global__ __launch_bounds__(256) void k_out_mlp(
    const float* __restrict__ w1, const float* __restrict__ b1,
    const float* __restrict__ w2, const float* __restrict__ b2)
{
    __shared__ float a0[4][68];
    __shared__ float t1[4][68];
    __shared__ float wt[64*65];
    int tid = threadIdx.x;
    int r = tid >> 6, c = tid & 63;
    int row = blockIdx.x*4 + r;

    a0[r][c] = g_agg[row*64 + c];
#pragma unroll
    for (int i = 0; i < 16; i++) {
        int idx = i*256 + tid;
        int cc = idx >> 6, kk = idx & 63;
        wt[kk*65 + cc] = w1[idx];
    }
    __syncthreads();
    float a = __ldg(&b1[c]);
#pragma unroll
    for (int k = 0; k < 64; k += 4) {
        float4 h4 = *(const float4*)&a0[r][k];
        a = fmaf(h4.x, wt[(k  )*65 + c], a);
        a = fmaf(h4.y, wt[(k+1)*65 + c], a);
        a = fmaf(h4.z, wt[(k+2)*65 + c], a);
        a = fmaf(h4.w, wt[(k+3)*65 + c], a);
    }
    t1[r][c] = leaky(a);
    __syncthreads();
#pragma unroll
    for (int i = 0; i < 16; i++) {
        int idx = i*256 + tid;
        int cc = idx >> 6, kk = idx & 63;
        wt[kk*65 + cc] = w2[idx];
    }
    __syncthreads();
    float a2 = __ldg(&b2[c]);
#pragma unroll
    for (int k = 0; k < 64; k += 4) {
        float4 h4 = *(const float4*)&t1[r][k];
        a2 = fmaf(h4.x, wt[(k  )*65 + c], a2);
        a2 = fmaf(h4.y, wt[(k+1)*65 + c], a2);
        a2 = fmaf(h4.z, wt[(k+2)*65 + c], a2);
        a2 = fmaf(h4.w, wt[(k+3)*65 + c], a2);
    }
    g_o[row*64 + c] = leaky(a2);
}

// ---------------- K7: final norm + residual (stats combined inline) ----------------
__global__ __launch_bounds__(256) void k_finalize(
    const float* __restrict__ feat,
    const float* __restrict__ gam, const float* __restrict__ bet,
    const float* __restrict__ wres, const float* __restrict__ bres,
    float* __restrict__ out)
{
    int idx = blockIdx.x * 256 + threadIdx.x;
    int row = idx >> 6, c = idx & 63;
    float mu, rs;
    stats_combine(c >> 4, mu, rs);
    float x = (g_o[idx] - mu) * rs;
    x = fmaf(x, __ldg(&gam[c]), __ldg(&bet[c]));
    float a = __ldg(&bres[c]);
#pragma unroll
    for (int k4 = 0; k4 < 4; k4++) {
        float4 f = __ldg((const float4*)&feat[row*16 + k4*4]);
        float4 w = __ldg((const float4*)&wres[c*16 + k4*4]);
        a = fmaf(f.x,w.x,a); a = fmaf(f.y,w.y,a); a = fmaf(f.z,w.z,a); a = fmaf(f.w,w.w,a);
    }
    out[idx] = x + a;
}

extern "C" void kernel_launch(void* const* d_in, const int* in_sizes, int n_in,
                              void* d_out, int out_size)
{
    const float* points   = (const float*)d_in[0];
    const float* nuv      = (const float*)d_in[1];
    const float* features = (const float*)d_in[2];
    const float* w_in1    = (const float*)d_in[3];
    const float* b_in1    = (const float*)d_in[4];
    const float* w_in2    = (const float*)d_in[5];
    const float* b_in2    = (const float*)d_in[6];
    const float* g_in     = (const float*)d_in[7];
    const float* be_in    = (const float*)d_in[8];
    const float* wq       = (const float*)d_in[9];
    const float* bq       = (const float*)d_in[10];
    const float* wk       = (const float*)d_in[11];
    const float* bk       = (const float*)d_in[12];
    const float* wv       = (const float*)d_in[13];
    const float* bv       = (const float*)d_in[14];
    const float* conv_w1  = (const float*)d_in[15];
    const float* conv_b1  = (const float*)d_in[16];
    const float* conv_w2  = (const float*)d_in[17];
    const float* conv_b2  = (const float*)d_in[18];
    const float* rls      = (const float*)d_in[19];
    const float* rbf_a    = (const float*)d_in[20];
    const float* rbf_b    = (const float*)d_in[21];
    const float* rbf_c    = (const float*)d_in[22];
    const float* w_o1     = (const float*)d_in[23];
    const float* b_o1     = (const float*)d_in[24];
    const float* w_o2     = (const float*)d_in[25];
    const float* b_o2     = (const float*)d_in[26];
    const float* g_out    = (const float*)d_in[27];
    const float* be_out   = (const float*)d_in[28];
    const float* w_res    = (const float*)d_in[29];
    const float* b_res    = (const float*)d_in[30];

    k_in_mlp<<<NPTS/4, 256>>>(features, w_in1, b_in1, w_in2, b_in2);
    k_stats_part<<<NPART, 256>>>(0, points, nuv);
    k_qkv<<<NPTS/4, 256>>>(wq, bq, wk, bk, wv, bv, g_in, be_in);
    k_attn<<<NPTS, 256>>>(points, nuv, conv_w1, conv_b1, conv_w2, conv_b2,
                          rls, rbf_a, rbf_b, rbf_c);
    k_out_mlp<<<NPTS/4, 256>>>(w_o1, b_o1, w_o2, b_o2);
    k_stats_part<<<NPART, 256>>>(1, points, nuv);
    k_finalize<<<NPTS*64/256, 256>>>(features, g_out, be_out, w_res, b_res, (float*)d_out);
}

// round 12
// speedup vs baseline: 1.4365x; 1.0597x over previous
#include <cuda_runtime.h>
#include <cuda_fp16.h>

#define NPTS 1600
#define HIDC 64
#define TILE 256
#define NPART 25

__device__ float g_h[NPTS*HIDC];     // pre-norm hidden
__device__ float g_Q[NPTS*HIDC];
__device__ uint4 g_K4h[8*NPTS];      // [h*NPTS + j] = 8 halves of K (head-row)
__device__ uint4 g_V4h[8*NPTS];      // [h*NPTS + j] = 8 halves of V (head-row)
__device__ float4 g_p4[NPTS];        // {px,py,pz,n0}
__device__ float2 g_n2[NPTS];        // {n1,n2}
__device__ float g_agg[NPTS*HIDC];   // attention output
__device__ float g_o[NPTS*HIDC];     // pre-norm output MLP
__device__ float g_part[NPART*8];    // partial stats

__device__ __forceinline__ float leaky(float x) { return x >= 0.f ? x : 0.2f * x; }

// ---------------- K1: input MLP (pre-norm), smem-staged weights ----------------
__global__ __launch_bounds__(256) void k_in_mlp(
    const float* __restrict__ feat,
    const float* __restrict__ w1, const float* __restrict__ b1,
    const float* __restrict__ w2, const float* __restrict__ b2)
{
    __shared__ float sf[4][16];
    __shared__ float t1[4][68];
    __shared__ float wt[64*65];
    int tid = threadIdx.x;
    int r = tid >> 6, c = tid & 63;
    int row = blockIdx.x*4 + r;

    if (tid < 64) sf[tid >> 4][tid & 15] = feat[blockIdx.x*64 + tid];
#pragma unroll
    for (int i = 0; i < 4; i++) {
        int idx = i*256 + tid;
        int cc = idx >> 4, kk = idx & 15;
        wt[kk*65 + cc] = w1[idx];
    }
    __syncthreads();
    float a = __ldg(&b1[c]);
#pragma unroll
    for (int k = 0; k < 16; k++) a = fmaf(sf[r][k], wt[k*65 + c], a);
    t1[r][c] = leaky(a);
    __syncthreads();
#pragma unroll
    for (int i = 0; i < 16; i++) {
        int idx = i*256 + tid;
        int cc = idx >> 6, kk = idx & 63;
        wt[kk*65 + cc] = w2[idx];
    }
    __syncthreads();
    float a2 = __ldg(&b2[c]);
#pragma unroll
    for (int k = 0; k < 64; k += 4) {
        float4 h4 = *(const float4*)&t1[r][k];
        a2 = fmaf(h4.x, wt[(k  )*65 + c], a2);
        a2 = fmaf(h4.y, wt[(k+1)*65 + c], a2);
        a2 = fmaf(h4.z, wt[(k+2)*65 + c], a2);
        a2 = fmaf(h4.w, wt[(k+3)*65 + c], a2);
    }
    g_h[row*64 + c] = leaky(a2);
}

// ---------------- stats: parallel partial (+ geometry pack on pass 0) ----------------
__global__ __launch_bounds__(256) void k_stats_part(
    int which, const float* __restrict__ points, const float* __restrict__ nuv)
{
    if (which == 0) {
        int p = blockIdx.x*256 + threadIdx.x;
        if (p < NPTS) {
            g_p4[p] = make_float4(points[p*3+0], points[p*3+1], points[p*3+2], nuv[p*9+0]);
            g_n2[p] = make_float2(nuv[p*9+1], nuv[p*9+2]);
        }
    }
    const float4* src = (const float4*)(which ? g_o : g_h);
    float s[4] = {0,0,0,0}, q[4] = {0,0,0,0};
#pragma unroll
    for (int k = 0; k < 4; k++) {
        int idx = blockIdx.x*1024 + k*256 + threadIdx.x;
        float4 v = src[idx];
        int g = (idx & 15) >> 2;
        s[g] += v.x + v.y + v.z + v.w;
        q[g] += v.x*v.x + v.y*v.y + v.z*v.z + v.w*v.w;
    }
    __shared__ float red[256][8];
#pragma unroll
    for (int g = 0; g < 4; g++) { red[threadIdx.x][g] = s[g]; red[threadIdx.x][4+g] = q[g]; }
    __syncthreads();
    for (int st = 128; st > 0; st >>= 1) {
        if (threadIdx.x < st)
#pragma unroll
            for (int k = 0; k < 8; k++) red[threadIdx.x][k] += red[threadIdx.x + st][k];
        __syncthreads();
    }
    if (threadIdx.x < 8) g_part[blockIdx.x*8 + threadIdx.x] = red[0][threadIdx.x];
}

// combine partials for group g -> mu, rs
__device__ __forceinline__ void stats_combine(int g, float& mu, float& rs)
{
    float s = 0.f, q = 0.f;
#pragma unroll
    for (int b = 0; b < NPART; b++) { s += g_part[b*8 + g]; q += g_part[b*8 + 4 + g]; }
    const float invn = 1.f / (NPTS * 16.f);
    mu = s * invn;
    float var = q * invn - mu*mu;
    rs = rsqrtf(var + 1e-5f);
}

// ---------------- K3: normalize + QKV (smem-staged; K,V fp16 head-row packed) ----------------
__global__ __launch_bounds__(256) void k_qkv(
    const float* __restrict__ wq, const float* __restrict__ bq,
    const float* __restrict__ wk, const float* __restrict__ bk,
    const float* __restrict__ wv, const float* __restrict__ bv,
    const float* __restrict__ gam, const float* __restrict__ bet)
{
    __shared__ float hn[4][68];
    __shared__ float wt[64*65];
    __shared__ float sK[4][64];
    __shared__ float sV[4][64];
    int tid = threadIdx.x;
    int r = tid >> 6, c = tid & 63;
    int row = blockIdx.x*4 + r;

    {
        float mu, rs;
        stats_combine(c >> 4, mu, rs);
        float x = g_h[row*64 + c];
        float v = (x - mu) * rs;
        hn[r][c] = fmaf(v, __ldg(&gam[c]), __ldg(&bet[c]));
    }

    const float* Ws[3] = {wq, wk, wv};
    const float* Bs[3] = {bq, bk, bv};
#pragma unroll
    for (int mtx = 0; mtx < 3; mtx++) {
        __syncthreads();
#pragma unroll
        for (int i = 0; i < 16; i++) {
            int idx = i*256 + tid;
            int cc = idx >> 6, kk = idx & 63;
            wt[kk*65 + cc] = Ws[mtx][idx];
        }
        __syncthreads();
        float a = __ldg(&Bs[mtx][c]);
#pragma unroll
        for (int k = 0; k < 64; k += 4) {
            float4 h4 = *(const float4*)&hn[r][k];
            a = fmaf(h4.x, wt[(k  )*65 + c], a);
            a = fmaf(h4.y, wt[(k+1)*65 + c], a);
            a = fmaf(h4.z, wt[(k+2)*65 + c], a);
            a = fmaf(h4.w, wt[(k+3)*65 + c], a);
        }
        if (mtx == 0)      g_Q[row*64 + c] = a;
        else if (mtx == 1) sK[r][c] = a;
        else               sV[r][c] = a;
    }
    __syncthreads();
    // pack head-row fp16: 128 threads = 4 rows x 8 heads x 4 uints
    if (tid < 128) {
        int rr = tid >> 5, hh = (tid >> 2) & 7, t = tid & 3;
        int rw = blockIdx.x*4 + rr;
        __half2 kh = __floats2half2_rn(sK[rr][hh*8 + 2*t], sK[rr][hh*8 + 2*t + 1]);
        __half2 vh = __floats2half2_rn(sV[rr][hh*8 + 2*t], sV[rr][hh*8 + 2*t + 1]);
        ((unsigned int*)g_K4h)[(hh*NPTS + rw)*4 + t] = *(unsigned int*)&kh;
        ((unsigned int*)g_V4h)[(hh*NPTS + rw)*4 + t] = *(unsigned int*)&vh;
    }
}

// ---------------- K4: fused pairwise geometry + conv + attention (pipelined, HMMA conv) ----------------
// stage-1: geometry + RBF + conv1 for point j (inputs preloaded), write packed F1 + W
__device__ __forceinline__ void stage1_compute(
    const float4 pj, const float2 nj,
    const float* sPi, const float* sNuv,
    const float* sw1, const float* sb1,
    const float* sra, const float* srb, const float* src, float inv2s2,
    uint4* outF, float* outW)
{
    const float INVS = 0.11785113019775793f;   // 1/(sqrt(2)*6)
    float dx = (pj.x - sPi[0]) * INVS;
    float dy = (pj.y - sPi[1]) * INVS;
    float dz = (pj.z - sPi[2]) * INVS;
    float ndot = sNuv[0]*pj.w + sNuv[1]*nj.x + sNuv[2]*nj.y;
    float u = 2.f - ndot;
    float d2 = (dx*dx + dy*dy + dz*dz) * u * u;
    float t = 1.f / (1.f + d2 * (1.f/3.f));
    *outW = t*t*t;
    float bd = sqrtf(d2);
    float X[8];
    X[0] = sNuv[0]*dx + sNuv[1]*dy + sNuv[2]*dz;
    X[1] = sNuv[3]*dx + sNuv[4]*dy + sNuv[5]*dz;
    X[2] = sNuv[6]*dx + sNuv[7]*dy + sNuv[8]*dz;
    X[3] = ndot;
    float rp0 = srb[0], rp1 = srb[1], rp2 = srb[2], rp3 = srb[3];
#pragma unroll
    for (int r = 0; r < 8; r++) {
        float dd = bd - src[r];
        float e = __expf(-dd*dd * inv2s2);
        rp0 = fmaf(e, sra[0*8+r], rp0);
        rp1 = fmaf(e, sra[1*8+r], rp1);
        rp2 = fmaf(e, sra[2*8+r], rp2);
        rp3 = fmaf(e, sra[3*8+r], rp3);
    }
    X[4] = rp0; X[5] = rp1; X[6] = rp2; X[7] = rp3;
    float F[8];
#pragma unroll
    for (int c = 0; c < 8; c++) {
        float a = sb1[c];
#pragma unroll
        for (int k = 0; k < 8; k++) a = fmaf(X[k], sw1[c*8+k], a);
        F[c] = fmaxf(a, 0.f);
    }
    uint4 pkv;
    __half2 h01 = __floats2half2_rn(F[0], F[1]);
    __half2 h23 = __floats2half2_rn(F[2], F[3]);
    __half2 h45 = __floats2half2_rn(F[4], F[5]);
    __half2 h67 = __floats2half2_rn(F[6], F[7]);
    pkv.x = *(unsigned int*)&h01; pkv.y = *(unsigned int*)&h23;
    pkv.z = *(unsigned int*)&h45; pkv.w = *(unsigned int*)&h67;
    *outF = pkv;
}

__device__ __forceinline__ void mma16n8k8(
    float& d0, float& d1, float& d2, float& d3,
    unsigned int a0, unsigned int a1, unsigned int b0,
    float c0, float c1, float c2, float c3)
{
    asm volatile(
        "mma.sync.aligned.m16n8k8.row.col.f32.f16.f16.f32 "
        "{%0,%1,%2,%3}, {%4,%5}, {%6}, {%7,%8,%9,%10};"
        : "=f"(d0), "=f"(d1), "=f"(d2), "=f"(d3)
        : "r"(a0), "r"(a1), "r"(b0),
          "f"(c0), "f"(c1), "f"(c2), "f"(c3));
}

__global__ __launch_bounds__(256, 3) void k_attn(
    const float* __restrict__ points, const float* __restrict__ nuv,
    const float* __restrict__ cw1, const float* __restrict__ cb1,
    const float* __restrict__ cw2, const float* __restrict__ cb2,
    const float* __restrict__ rls, const float* __restrict__ ra,
    const float* __restrict__ rb, const float* __restrict__ rc)
{
    const float SCALE = 0.3535533905932738f;    // 1/sqrt(8)
    int i = blockIdx.x;
    int tid = threadIdx.x, warp = tid >> 5, lane = tid & 31;
    int g = lane >> 2, t = lane & 3;

    __shared__ uint4 sF1h[2][TILE];
    __shared__ float sWgt[2][TILE];
    __shared__ float sQ[64];
    __shared__ float sNuv[9], sPi[3];
    __shared__ float sw1[64], sb1[8], sra[32], srb[4], src[8], sInv2s2;

    if (tid < 64) { sw1[tid] = __ldg(&cw1[tid]); sQ[tid] = g_Q[i*64 + tid]; }
    if (tid < 8)  { sb1[tid] = __ldg(&cb1[tid]); src[tid] = __ldg(&rc[tid]); }
    if (tid < 32) sra[tid] = __ldg(&ra[tid]);
    if (tid < 4)  srb[tid] = __ldg(&rb[tid]);
    if (tid < 9)  sNuv[tid] = nuv[i*9 + tid];
    if (tid < 3)  sPi[tid]  = points[i*3 + tid];
    if (tid == 0) { float sg = fmaxf(__expf(__ldg(&rls[0])), 1e-6f); sInv2s2 = 0.5f/(sg*sg); }
    __syncthreads();

    // B fragment: b0 = {W2[c=g][k=2t], W2[g][2t+1]} for this head; bias in C operand
    unsigned int bfrag;
    {
        __half2 hb = __floats2half2_rn(__ldg(&cw2[(warp*8 + g)*8 + 2*t]),
                                       __ldg(&cw2[(warp*8 + g)*8 + 2*t + 1]));
        bfrag = *(unsigned int*)&hb;
    }
    float bias0 = __ldg(&cb2[warp*8 + 2*t]);
    float bias1 = __ldg(&cb2[warp*8 + 2*t + 1]);

    // Q half2 with scale folded
    __half2 qh2[4];
#pragma unroll
    for (int cp = 0; cp < 4; cp++)
        qh2[cp] = __floats2half2_rn(sQ[warp*8 + 2*cp] * SCALE, sQ[warp*8 + 2*cp + 1] * SCALE);

    float denom = 0.f;
    float acc0 = 0.f, acc1 = 0.f;   // partial sums for c = 2t, 2t+1

    const uint4* Kb = &g_K4h[warp*NPTS];
    const unsigned int* Vu = (const unsigned int*)&g_V4h[warp*NPTS];

    // prologue: stage-1 for tile 0
    {
        float4 pj = __ldg(&g_p4[tid]);
        float2 nj = __ldg(&g_n2[tid]);
        stage1_compute(pj, nj, sPi, sNuv, sw1, sb1, sra, srb, src, sInv2s2,
                       &sF1h[0][tid], &sWgt[0][tid]);
    }
    __syncthreads();

    int p = 0;
    for (int tb = 0; tb < NPTS; tb += TILE) {
        // prefetch next tile's geometry into registers
        int jn = tb + TILE + tid;
        bool pre = (jn < NPTS);
        float4 pj; float2 nj;
        if (pre) { pj = __ldg(&g_p4[jn]); nj = __ldg(&g_n2[jn]); }

        int ng = min(TILE, NPTS - tb) >> 5;   // groups of 32 (always exact: 8 or 2)
#pragma unroll 2
        for (int it = 0; it < ng; it++) {
            int sbase = it*32;
            int jb = tb + sbase;
            // --- e-phase: lane = j ---
            uint4 ku = __ldg(&Kb[jb + lane]);
            __half2 s0 = __hmul2(qh2[0], *(const __half2*)&ku.x);
            s0 = __hfma2(qh2[1], *(const __half2*)&ku.y, s0);
            __half2 s1 = __hmul2(qh2[2], *(const __half2*)&ku.z);
            s1 = __hfma2(qh2[3], *(const __half2*)&ku.w, s1);
            float2 sf = __half22float2(__hadd2(s0, s1));
            float e = __expf(sf.x + sf.y);
            denom += e;
            float ew = e * sWgt[p][sbase + lane];

            // --- fragment phase: Fh^T[32j x 8c] via 2x HMMA ---
            const unsigned int* F1u = (const unsigned int*)&sF1h[p][sbase];
            unsigned int a0 = F1u[(g     )*4 + t];
            unsigned int a1 = F1u[(g +  8)*4 + t];
            unsigned int a2 = F1u[(g + 16)*4 + t];
            unsigned int a3 = F1u[(g + 24)*4 + t];
            float ew0 = __shfl_sync(0xffffffffu, ew, g);
            float ew1 = __shfl_sync(0xffffffffu, ew, g + 8);
            float ew2 = __shfl_sync(0xffffffffu, ew, g + 16);
            float ew3 = __shfl_sync(0xffffffffu, ew, g + 24);

            float d0, d1, d2, d3;
            mma16n8k8(d0, d1, d2, d3, a0, a1, bfrag, bias0, bias1, bias0, bias1);
            {
                unsigned int v0 = __ldg(&Vu[(jb + g     )*4 + t]);
                unsigned int v1 = __ldg(&Vu[(jb + 8 + g )*4 + t]);
                float2 vf0 = __half22float2(*(const __half2*)&v0);
                float2 vf1 = __half22float2(*(const __half2*)&v1);
                acc0 = fmaf(ew0 * fmaxf(d0, 0.f), vf0.x, acc0);
                acc1 = fmaf(ew0 * fmaxf(d1, 0.f), vf0.y, acc1);
                acc0 = fmaf(ew1 * fmaxf(d2, 0.f), vf1.x, acc0);
                acc1 = fmaf(ew1 * fmaxf(d3, 0.f), vf1.y, acc1);
            }
            mma16n8k8(d0, d1, d2, d3, a2, a3, bfrag, bias0, bias1, bias0, bias1);
            {
                unsigned int v2 = __ldg(&Vu[(jb + 16 + g)*4 + t]);
                unsigned int v3 = __ldg(&Vu[(jb + 24 + g)*4 + t]);
                float2 vf2 = __half22float2(*(const __half2*)&v2);
                float2 vf3 = __half22float2(*(const __half2*)&v3);
                acc0 = fmaf(ew2 * fmaxf(d0, 0.f), vf2.x, acc0);
                acc1 = fmaf(ew2 * fmaxf(d1, 0.f), vf2.y, acc1);
                acc0 = fmaf(ew3 * fmaxf(d2, 0.f), vf3.x, acc0);
                acc1 = fmaf(ew3 * fmaxf(d3, 0.f), vf3.y, acc1);
            }
        }

        // stage 1: produce next buffer
        if (pre)
            stage1_compute(pj, nj, sPi, sNuv, sw1, sb1, sra, srb, src, sInv2s2,
                           &sF1h[p^1][tid], &sWgt[p^1][tid]);
        __syncthreads();
        p ^= 1;
    }

    // reductions: denom over full warp; acc over lanes sharing t (stride-4 classes)
#pragma unroll
    for (int o = 16; o > 0; o >>= 1) denom += __shfl_xor_sync(0xffffffffu, denom, o);
#pragma unroll
    for (int o = 4; o <= 16; o <<= 1) {
        acc0 += __shfl_xor_sync(0xffffffffu, acc0, o);
        acc1 += __shfl_xor_sync(0xffffffffu, acc1, o);
    }
    if (lane < 4) {
        float inv = 1.f / denom;
        g_agg[i*64 + warp*8 + 2*lane]     = acc0 * inv;
        g_agg[i*64 + warp*8 + 2*lane + 1] = acc1 * inv;
    }
}

// ---------------- K5: output MLP (pre-norm), smem-staged ----------------
__global__ __launch_bounds__(256) void k_out_mlp(
    const float* __restrict__ w1, const float* __restrict__ b1,
    const float* __restrict__ w2, const float* __restrict__ b2)
{
    __shared__ float a0[4][68];
    __shared__ float t1[4][68];
    __shared__ float wt[64*65];
    int tid = threadIdx.x;
    int r = tid >> 6, c = tid & 63;
    int row = blockIdx.x*4 + r;

    a0[r][c] = g_agg[row*64 + c];
#pragma unroll
    for (int i = 0; i < 16; i++) {
        int idx = i*256 + tid;
        int cc = idx >> 6, kk = idx & 63;
        wt[kk*65 + cc] = w1[idx];
    }
    __syncthreads();
    float a = __ldg(&b1[c]);
#pragma unroll
    for (int k = 0; k < 64; k += 4) {
        float4 h4 = *(const float4*)&a0[r][k];
        a = fmaf(h4.x, wt[(k  )*65 + c], a);
        a = fmaf(h4.y, wt[(k+1)*65 + c], a);
        a = fmaf(h4.z, wt[(k+2)*65 + c], a);
        a = fmaf(h4.w, wt[(k+3)*65 + c], a);
    }
    t1[r][c] = leaky(a);
    __syncthreads();
#pragma unroll
    for (int i = 0; i < 16; i++) {
        int idx = i*256 + tid;
        int cc = idx >> 6, kk = idx & 63;
        wt[kk*65 + cc] = w2[idx];
    }
    __syncthreads();
    float a2 = __ldg(&b2[c]);
#pragma unroll
    for (int k = 0; k < 64; k += 4) {
        float4 h4 = *(const float4*)&t1[r][k];
        a2 = fmaf(h4.x, wt[(k  )*65 + c], a2);
        a2 = fmaf(h4.y, wt[(k+1)*65 + c], a2);
        a2 = fmaf(h4.z, wt[(k+2)*65 + c], a2);
        a2 = fmaf(h4.w, wt[(k+3)*65 + c], a2);
    }
    g_o[row*64 + c] = leaky(a2);
}

// ---------------- K7: final norm + residual (stats combined inline) ----------------
__global__ __launch_bounds__(256) void k_finalize(
    const float* __restrict__ feat,
    const float* __restrict__ gam, const float* __restrict__ bet,
    const float* __restrict__ wres, const float* __restrict__ bres,
    float* __restrict__ out)
{
    int idx = blockIdx.x * 256 + threadIdx.x;
    int row = idx >> 6, c = idx & 63;
    float mu, rs;
    stats_combine(c >> 4, mu, rs);
    float x = (g_o[idx] - mu) * rs;
    x = fmaf(x, __ldg(&gam[c]), __ldg(&bet[c]));
    float a = __ldg(&bres[c]);
#pragma unroll
    for (int k4 = 0; k4 < 4; k4++) {
        float4 f = __ldg((const float4*)&feat[row*16 + k4*4]);
        float4 w = __ldg((const float4*)&wres[c*16 + k4*4]);
        a = fmaf(f.x,w.x,a); a = fmaf(f.y,w.y,a); a = fmaf(f.z,w.z,a); a = fmaf(f.w,w.w,a);
    }
    out[idx] = x + a;
}

extern "C" void kernel_launch(void* const* d_in, const int* in_sizes, int n_in,
                              void* d_out, int out_size)
{
    const float* points   = (const float*)d_in[0];
    const float* nuv      = (const float*)d_in[1];
    const float* features = (const float*)d_in[2];
    const float* w_in1    = (const float*)d_in[3];
    const float* b_in1    = (const float*)d_in[4];
    const float* w_in2    = (const float*)d_in[5];
    const float* b_in2    = (const float*)d_in[6];
    const float* g_in     = (const float*)d_in[7];
    const float* be_in    = (const float*)d_in[8];
    const float* wq       = (const float*)d_in[9];
    const float* bq       = (const float*)d_in[10];
    const float* wk       = (const float*)d_in[11];
    const float* bk       = (const float*)d_in[12];
    const float* wv       = (const float*)d_in[13];
    const float* bv       = (const float*)d_in[14];
    const float* conv_w1  = (const float*)d_in[15];
    const float* conv_b1  = (const float*)d_in[16];
    const float* conv_w2  = (const float*)d_in[17];
    const float* conv_b2  = (const float*)d_in[18];
    const float* rls      = (const float*)d_in[19];
    const float* rbf_a    = (const float*)d_in[20];
    const float* rbf_b    = (const float*)d_in[21];
    const float* rbf_c    = (const float*)d_in[22];
    const float* w_o1     = (const float*)d_in[23];
    const float* b_o1     = (const float*)d_in[24];
    const float* w_o2     = (const float*)d_in[25];
    const float* b_o2     = (const float*)d_in[26];
    const float* g_out    = (const float*)d_in[27];
    const float* be_out   = (const float*)d_in[28];
    const float* w_res    = (const float*)d_in[29];
    const float* b_res    = (const float*)d_in[30];

    k_in_mlp<<<NPTS/4, 256>>>(features, w_in1, b_in1, w_in2, b_in2);
    k_stats_part<<<NPART, 256>>>(0, points, nuv);
    k_qkv<<<NPTS/4, 256>>>(wq, bq, wk, bk, wv, bv, g_in, be_in);
    k_attn<<<NPTS, 256>>>(points, nuv, conv_w1, conv_b1, conv_w2, conv_b2,
                          rls, rbf_a, rbf_b, rbf_c);
    k_out_mlp<<<NPTS/4, 256>>>(w_o1, b_o1, w_o2, b_o2);
    k_stats_part<<<NPART, 256>>>(1, points, nuv);
    k_finalize<<<NPTS*64/256, 256>>>(features, g_out, be_out, w_res, b_res, (float*)d_out);
}

// round 13
// speedup vs baseline: 1.4494x; 1.0090x over previous
#include <cuda_runtime.h>
#include <cuda_fp16.h>

#define NPTS 1600
#define HIDC 64
#define TILE 256
#define NPART 25

__device__ float g_h[NPTS*HIDC];     // pre-norm hidden
__device__ float g_Q[NPTS*HIDC];
__device__ uint4 g_K4h[8*NPTS];      // [h*NPTS + j] = 8 halves of K (head-row)
__device__ uint4 g_V4h[8*NPTS];      // [h*NPTS + j] = 8 halves of V (head-row)
__device__ float4 g_p4[NPTS];        // {px,py,pz,n0}
__device__ float2 g_n2[NPTS];        // {n1,n2}
__device__ float g_agg[NPTS*HIDC];   // attention output
__device__ float g_o[NPTS*HIDC];     // pre-norm output MLP
__device__ float g_part[NPART*8];    // partial stats

__device__ __forceinline__ float leaky(float x) { return x >= 0.f ? x : 0.2f * x; }

__device__ __forceinline__ unsigned int smem_u32(const void* p) {
    unsigned int a;
    asm("{ .reg .u64 t; cvta.to.shared.u64 t, %1; cvt.u32.u64 %0, t; }" : "=r"(a) : "l"(p));
    return a;
}

// ---------------- K1: input MLP (pre-norm), smem-staged weights ----------------
__global__ __launch_bounds__(256) void k_in_mlp(
    const float* __restrict__ feat,
    const float* __restrict__ w1, const float* __restrict__ b1,
    const float* __restrict__ w2, const float* __restrict__ b2)
{
    __shared__ float sf[4][16];
    __shared__ float t1[4][68];
    __shared__ float wt[64*65];
    int tid = threadIdx.x;
    int r = tid >> 6, c = tid & 63;
    int row = blockIdx.x*4 + r;

    if (tid < 64) sf[tid >> 4][tid & 15] = feat[blockIdx.x*64 + tid];
#pragma unroll
    for (int i = 0; i < 4; i++) {
        int idx = i*256 + tid;
        int cc = idx >> 4, kk = idx & 15;
        wt[kk*65 + cc] = w1[idx];
    }
    __syncthreads();
    float a = __ldg(&b1[c]);
#pragma unroll
    for (int k = 0; k < 16; k++) a = fmaf(sf[r][k], wt[k*65 + c], a);
    t1[r][c] = leaky(a);
    __syncthreads();
#pragma unroll
    for (int i = 0; i < 16; i++) {
        int idx = i*256 + tid;
        int cc = idx >> 6, kk = idx & 63;
        wt[kk*65 + cc] = w2[idx];
    }
    __syncthreads();
    float a2 = __ldg(&b2[c]);
#pragma unroll
    for (int k = 0; k < 64; k += 4) {
        float4 h4 = *(const float4*)&t1[r][k];
        a2 = fmaf(h4.x, wt[(k  )*65 + c], a2);
        a2 = fmaf(h4.y, wt[(k+1)*65 + c], a2);
        a2 = fmaf(h4.z, wt[(k+2)*65 + c], a2);
        a2 = fmaf(h4.w, wt[(k+3)*65 + c], a2);
    }
    g_h[row*64 + c] = leaky(a2);
}

// ---------------- stats: parallel partial (+ geometry pack on pass 0) ----------------
__global__ __launch_bounds__(256) void k_stats_part(
    int which, const float* __restrict__ points, const float* __restrict__ nuv)
{
    if (which == 0) {
        int p = blockIdx.x*256 + threadIdx.x;
        if (p < NPTS) {
            g_p4[p] = make_float4(points[p*3+0], points[p*3+1], points[p*3+2], nuv[p*9+0]);
            g_n2[p] = make_float2(nuv[p*9+1], nuv[p*9+2]);
        }
    }
    const float4* src = (const float4*)(which ? g_o : g_h);
    float s[4] = {0,0,0,0}, q[4] = {0,0,0,0};
#pragma unroll
    for (int k = 0; k < 4; k++) {
        int idx = blockIdx.x*1024 + k*256 + threadIdx.x;
        float4 v = src[idx];
        int g = (idx & 15) >> 2;
        s[g] += v.x + v.y + v.z + v.w;
        q[g] += v.x*v.x + v.y*v.y + v.z*v.z + v.w*v.w;
    }
    __shared__ float red[256][8];
#pragma unroll
    for (int g = 0; g < 4; g++) { red[threadIdx.x][g] = s[g]; red[threadIdx.x][4+g] = q[g]; }
    __syncthreads();
    for (int st = 128; st > 0; st >>= 1) {
        if (threadIdx.x < st)
#pragma unroll
            for (int k = 0; k < 8; k++) red[threadIdx.x][k] += red[threadIdx.x + st][k];
        __syncthreads();
    }
    if (threadIdx.x < 8) g_part[blockIdx.x*8 + threadIdx.x] = red[0][threadIdx.x];
}

// combine partials for group g -> mu, rs
__device__ __forceinline__ void stats_combine(int g, float& mu, float& rs)
{
    float s = 0.f, q = 0.f;
#pragma unroll
    for (int b = 0; b < NPART; b++) { s += g_part[b*8 + g]; q += g_part[b*8 + 4 + g]; }
    const float invn = 1.f / (NPTS * 16.f);
    mu = s * invn;
    float var = q * invn - mu*mu;
    rs = rsqrtf(var + 1e-5f);
}

// ---------------- K3: normalize + QKV (smem-staged; K,V fp16 head-row packed) ----------------
__global__ __launch_bounds__(256) void k_qkv(
    const float* __restrict__ wq, const float* __restrict__ bq,
    const float* __restrict__ wk, const float* __restrict__ bk,
    const float* __restrict__ wv, const float* __restrict__ bv,
    const float* __restrict__ gam, const float* __restrict__ bet)
{
    __shared__ float hn[4][68];
    __shared__ float wt[64*65];
    __shared__ float sK[4][64];
    __shared__ float sV[4][64];
    int tid = threadIdx.x;
    int r = tid >> 6, c = tid & 63;
    int row = blockIdx.x*4 + r;

    {
        float mu, rs;
        stats_combine(c >> 4, mu, rs);
        float x = g_h[row*64 + c];
        float v = (x - mu) * rs;
        hn[r][c] = fmaf(v, __ldg(&gam[c]), __ldg(&bet[c]));
    }

    const float* Ws[3] = {wq, wk, wv};
    const float* Bs[3] = {bq, bk, bv};
#pragma unroll
    for (int mtx = 0; mtx < 3; mtx++) {
        __syncthreads();
#pragma unroll
        for (int i = 0; i < 16; i++) {
            int idx = i*256 + tid;
            int cc = idx >> 6, kk = idx & 63;
            wt[kk*65 + cc] = Ws[mtx][idx];
        }
        __syncthreads();
        float a = __ldg(&Bs[mtx][c]);
#pragma unroll
        for (int k = 0; k < 64; k += 4) {
            float4 h4 = *(const float4*)&hn[r][k];
            a = fmaf(h4.x, wt[(k  )*65 + c], a);
            a = fmaf(h4.y, wt[(k+1)*65 + c], a);
            a = fmaf(h4.z, wt[(k+2)*65 + c], a);
            a = fmaf(h4.w, wt[(k+3)*65 + c], a);
        }
        if (mtx == 0)      g_Q[row*64 + c] = a;
        else if (mtx == 1) sK[r][c] = a;
        else               sV[r][c] = a;
    }
    __syncthreads();
    // pack head-row fp16: 128 threads = 4 rows x 8 heads x 4 uints
    if (tid < 128) {
        int rr = tid >> 5, hh = (tid >> 2) & 7, t = tid & 3;
        int rw = blockIdx.x*4 + rr;
        __half2 kh = __floats2half2_rn(sK[rr][hh*8 + 2*t], sK[rr][hh*8 + 2*t + 1]);
        __half2 vh = __floats2half2_rn(sV[rr][hh*8 + 2*t], sV[rr][hh*8 + 2*t + 1]);
        ((unsigned int*)g_K4h)[(hh*NPTS + rw)*4 + t] = *(unsigned int*)&kh;
        ((unsigned int*)g_V4h)[(hh*NPTS + rw)*4 + t] = *(unsigned int*)&vh;
    }
}

// ---------------- K4: fused pairwise geometry + conv + attention (pipelined, HMMA + LDSM) ----------------
// stage-1: geometry + RBF + conv1 for point j (inputs preloaded), write packed F1 + W
__device__ __forceinline__ void stage1_compute(
    const float4 pj, const float2 nj,
    const float* sPi, const float* sNuv,
    const float* sw1, const float* sb1,
    const float* sra, const float* srb, const float* src, float inv2s2,
    uint4* outF, float* outW)
{
    const float INVS = 0.11785113019775793f;   // 1/(sqrt(2)*6)
    float dx = (pj.x - sPi[0]) * INVS;
    float dy = (pj.y - sPi[1]) * INVS;
    float dz = (pj.z - sPi[2]) * INVS;
    float ndot = sNuv[0]*pj.w + sNuv[1]*nj.x + sNuv[2]*nj.y;
    float u = 2.f - ndot;
    float d2 = (dx*dx + dy*dy + dz*dz) * u * u;
    float t = 1.f / (1.f + d2 * (1.f/3.f));
    *outW = t*t*t;
    float bd = sqrtf(d2);
    float X[8];
    X[0] = sNuv[0]*dx + sNuv[1]*dy + sNuv[2]*dz;
    X[1] = sNuv[3]*dx + sNuv[4]*dy + sNuv[5]*dz;
    X[2] = sNuv[6]*dx + sNuv[7]*dy + sNuv[8]*dz;
    X[3] = ndot;
    float rp0 = srb[0], rp1 = srb[1], rp2 = srb[2], rp3 = srb[3];
#pragma unroll
    for (int r = 0; r < 8; r++) {
        float dd = bd - src[r];
        float e = __expf(-dd*dd * inv2s2);
        rp0 = fmaf(e, sra[0*8+r], rp0);
        rp1 = fmaf(e, sra[1*8+r], rp1);
        rp2 = fmaf(e, sra[2*8+r], rp2);
        rp3 = fmaf(e, sra[3*8+r], rp3);
    }
    X[4] = rp0; X[5] = rp1; X[6] = rp2; X[7] = rp3;
    float F[8];
#pragma unroll
    for (int c = 0; c < 8; c++) {
        float a = sb1[c];
#pragma unroll
        for (int k = 0; k < 8; k++) a = fmaf(X[k], sw1[c*8+k], a);
        F[c] = fmaxf(a, 0.f);
    }
    uint4 pkv;
    __half2 h01 = __floats2half2_rn(F[0], F[1]);
    __half2 h23 = __floats2half2_rn(F[2], F[3]);
    __half2 h45 = __floats2half2_rn(F[4], F[5]);
    __half2 h67 = __floats2half2_rn(F[6], F[7]);
    pkv.x = *(unsigned int*)&h01; pkv.y = *(unsigned int*)&h23;
    pkv.z = *(unsigned int*)&h45; pkv.w = *(unsigned int*)&h67;
    *outF = pkv;
}

__device__ __forceinline__ void mma16n8k8(
    float& d0, float& d1, float& d2, float& d3,
    unsigned int a0, unsigned int a1, unsigned int b0,
    float c0, float c1, float c2, float c3)
{
    asm volatile(
        "mma.sync.aligned.m16n8k8.row.col.f32.f16.f16.f32 "
        "{%0,%1,%2,%3}, {%4,%5}, {%6}, {%7,%8,%9,%10};"
        : "=f"(d0), "=f"(d1), "=f"(d2), "=f"(d3)
        : "r"(a0), "r"(a1), "r"(b0),
          "f"(c0), "f"(c1), "f"(c2), "f"(c3));
}

__global__ __launch_bounds__(256, 3) void k_attn(
    const float* __restrict__ points, const float* __restrict__ nuv,
    const float* __restrict__ cw1, const float* __restrict__ cb1,
    const float* __restrict__ cw2, const float* __restrict__ cb2,
    const float* __restrict__ rls, const float* __restrict__ ra,
    const float* __restrict__ rb, const float* __restrict__ rc)
{
    // 1/sqrt(8) * log2(e): exp(x) == exp2(x*log2e), folded into Q scale
    const float SCALE_L2E = 0.3535533905932738f * 1.4426950408889634f;
    int i = blockIdx.x;
    int tid = threadIdx.x, warp = tid >> 5, lane = tid & 31;
    int g = lane >> 2, t = lane & 3;

    __shared__ uint4 sF1h[2][TILE];
    __shared__ float sWgt[2][TILE];
    __shared__ float sQ[64];
    __shared__ float sNuv[9], sPi[3];
    __shared__ float sw1[64], sb1[8], sra[32], srb[4], src[8], sInv2s2;

    if (tid < 64) { sw1[tid] = __ldg(&cw1[tid]); sQ[tid] = g_Q[i*64 + tid]; }
    if (tid < 8)  { sb1[tid] = __ldg(&cb1[tid]); src[tid] = __ldg(&rc[tid]); }
    if (tid < 32) sra[tid] = __ldg(&ra[tid]);
    if (tid < 4)  srb[tid] = __ldg(&rb[tid]);
    if (tid < 9)  sNuv[tid] = nuv[i*9 + tid];
    if (tid < 3)  sPi[tid]  = points[i*3 + tid];
    if (tid == 0) { float sg = fmaxf(__expf(__ldg(&rls[0])), 1e-6f); sInv2s2 = 0.5f/(sg*sg); }
    __syncthreads();

    // B fragment: b0 = {W2[c=g][k=2t], W2[g][2t+1]} for this head; bias in C operand
    unsigned int bfrag;
    {
        __half2 hb = __floats2half2_rn(__ldg(&cw2[(warp*8 + g)*8 + 2*t]),
                                       __ldg(&cw2[(warp*8 + g)*8 + 2*t + 1]));
        bfrag = *(unsigned int*)&hb;
    }
    float bias0 = __ldg(&cb2[warp*8 + 2*t]);
    float bias1 = __ldg(&cb2[warp*8 + 2*t + 1]);

    // Q half2 with scale*log2e folded
    __half2 qh2[4];
#pragma unroll
    for (int cp = 0; cp < 4; cp++)
        qh2[cp] = __floats2half2_rn(sQ[warp*8 + 2*cp] * SCALE_L2E, sQ[warp*8 + 2*cp + 1] * SCALE_L2E);

    float denom = 0.f;
    float acc0 = 0.f, acc1 = 0.f;   // partial sums for c = 2t, 2t+1

    const uint4* Kb = &g_K4h[warp*NPTS];
    const unsigned int* Vu = (const unsigned int*)&g_V4h[warp*NPTS];

    // smem base for ldmatrix row addresses (lane -> row lane of current group)
    unsigned int f1b0 = smem_u32(&sF1h[0][0]) + (unsigned)lane * 16u;

    // prologue: stage-1 for tile 0
    {
        float4 pj = __ldg(&g_p4[tid]);
        float2 nj = __ldg(&g_n2[tid]);
        stage1_compute(pj, nj, sPi, sNuv, sw1, sb1, sra, srb, src, sInv2s2,
                       &sF1h[0][tid], &sWgt[0][tid]);
    }
    __syncthreads();

    int p = 0;
    for (int tb = 0; tb < NPTS; tb += TILE) {
        // prefetch next tile's geometry into registers
        int jn = tb + TILE + tid;
        bool pre = (jn < NPTS);
        float4 pj; float2 nj;
        if (pre) { pj = __ldg(&g_p4[jn]); nj = __ldg(&g_n2[jn]); }

        unsigned int f1base = f1b0 + (unsigned)p * (TILE * 16u);
        int ng = min(TILE, NPTS - tb) >> 5;   // groups of 32 (always exact: 8 or 2)
#pragma unroll 2
        for (int it = 0; it < ng; it++) {
            int sbase = it*32;
            int jb = tb + sbase;
            // --- e-phase: lane = j ---
            uint4 ku = __ldg(&Kb[jb + lane]);
            __half2 s0 = __hmul2(qh2[0], *(const __half2*)&ku.x);
            s0 = __hfma2(qh2[1], *(const __half2*)&ku.y, s0);
            __half2 s1 = __hmul2(qh2[2], *(const __half2*)&ku.z);
            s1 = __hfma2(qh2[3], *(const __half2*)&ku.w, s1);
            float2 sf = __half22float2(__hadd2(s0, s1));
            float sc = sf.x + sf.y;
            float e;
            asm("ex2.approx.f32 %0, %1;" : "=f"(e) : "f"(sc));
            denom += e;
            float ew = e * sWgt[p][sbase + lane];

            // --- fragment phase: ldmatrix x4 (rows sbase..sbase+31) ---
            unsigned int a0, a1, a2, a3;
            asm volatile(
                "ldmatrix.sync.aligned.m8n8.x4.shared.b16 {%0,%1,%2,%3}, [%4];"
                : "=r"(a0), "=r"(a1), "=r"(a2), "=r"(a3)
                : "r"(f1base + (unsigned)sbase * 16u));
            float ew0 = __shfl_sync(0xffffffffu, ew, g);
            float ew1 = __shfl_sync(0xffffffffu, ew, g + 8);
            float ew2 = __shfl_sync(0xffffffffu, ew, g + 16);
            float ew3 = __shfl_sync(0xffffffffu, ew, g + 24);

            float d0, d1, d2, d3;
            mma16n8k8(d0, d1, d2, d3, a0, a1, bfrag, bias0, bias1, bias0, bias1);
            {
                unsigned int v0 = __ldg(&Vu[(jb + g     )*4 + t]);
                unsigned int v1 = __ldg(&Vu[(jb + 8 + g )*4 + t]);
                float2 vf0 = __half22float2(*(const __half2*)&v0);
                float2 vf1 = __half22float2(*(const __half2*)&v1);
                acc0 = fmaf(ew0 * fmaxf(d0, 0.f), vf0.x, acc0);
                acc1 = fmaf(ew0 * fmaxf(d1, 0.f), vf0.y, acc1);
                acc0 = fmaf(ew1 * fmaxf(d2, 0.f), vf1.x, acc0);
                acc1 = fmaf(ew1 * fmaxf(d3, 0.f), vf1.y, acc1);
            }
            mma16n8k8(d0, d1, d2, d3, a2, a3, bfrag, bias0, bias1, bias0, bias1);
            {
                unsigned int v2 = __ldg(&Vu[(jb + 16 + g)*4 + t]);
                unsigned int v3 = __ldg(&Vu[(jb + 24 + g)*4 + t]);
                float2 vf2 = __half22float2(*(const __half2*)&v2);
                float2 vf3 = __half22float2(*(const __half2*)&v3);
                acc0 = fmaf(ew2 * fmaxf(d0, 0.f), vf2.x, acc0);
                acc1 = fmaf(ew2 * fmaxf(d1, 0.f), vf2.y, acc1);
                acc0 = fmaf(ew3 * fmaxf(d2, 0.f), vf3.x, acc0);
                acc1 = fmaf(ew3 * fmaxf(d3, 0.f), vf3.y, acc1);
            }
        }

        // stage 1: produce next buffer
        if (pre)
            stage1_compute(pj, nj, sPi, sNuv, sw1, sb1, sra, srb, src, sInv2s2,
                           &sF1h[p^1][tid], &sWgt[p^1][tid]);
        __syncthreads();
        p ^= 1;
    }

    // reductions: denom over full warp; acc over lanes sharing t (stride-4 classes)
#pragma unroll
    for (int o = 16; o > 0; o >>= 1) denom += __shfl_xor_sync(0xffffffffu, denom, o);
#pragma unroll
    for (int o = 4; o <= 16; o <<= 1) {
        acc0 += __shfl_xor_sync(0xffffffffu, acc0, o);
        acc1 += __shfl_xor_sync(0xffffffffu, acc1, o);
    }
    if (lane < 4) {
        float inv = 1.f / denom;
        g_agg[i*64 + warp*8 + 2*lane]     = acc0 * inv;
        g_agg[i*64 + warp*8 + 2*lane + 1] = acc1 * inv;
    }
}

// ---------------- K5: output MLP (pre-norm), smem-staged ----------------
__global__ __launch_bounds__(256) void k_out_mlp(
    const float* __restrict__ w1, const float* __restrict__ b1,
    const float* __restrict__ w2, const float* __restrict__ b2)
{
    __shared__ float a0[4][68];
    __shared__ float t1[4][68];
    __shared__ float wt[64*65];
    int tid = threadIdx.x;
    int r = tid >> 6, c = tid & 63;
    int row = blockIdx.x*4 + r;

    a0[r][c] = g_agg[row*64 + c];
#pragma unroll
    for (int i = 0; i < 16; i++) {
        int idx = i*256 + tid;
        int cc = idx >> 6, kk = idx & 63;
        wt[kk*65 + cc] = w1[idx];
    }
    __syncthreads();
    float a = __ldg(&b1[c]);
#pragma unroll
    for (int k = 0; k < 64; k += 4) {
        float4 h4 = *(const float4*)&a0[r][k];
        a = fmaf(h4.x, wt[(k  )*65 + c], a);
        a = fmaf(h4.y, wt[(k+1)*65 + c], a);
        a = fmaf(h4.z, wt[(k+2)*65 + c], a);
        a = fmaf(h4.w, wt[(k+3)*65 + c], a);
    }
    t1[r][c] = leaky(a);
    __syncthreads();
#pragma unroll
    for (int i = 0; i < 16; i++) {
        int idx = i*256 + tid;
        int cc = idx >> 6, kk = idx & 63;
        wt[kk*65 + cc] = w2[idx];
    }
    __syncthreads();
    float a2 = __ldg(&b2[c]);
#pragma unroll
    for (int k = 0; k < 64; k += 4) {
        float4 h4 = *(const float4*)&t1[r][k];
        a2 = fmaf(h4.x, wt[(k  )*65 + c], a2);
        a2 = fmaf(h4.y, wt[(k+1)*65 + c], a2);
        a2 = fmaf(h4.z, wt[(k+2)*65 + c], a2);
        a2 = fmaf(h4.w, wt[(k+3)*65 + c], a2);
    }
    g_o[row*64 + c] = leaky(a2);
}

// ---------------- K7: final norm + residual (stats combined inline) ----------------
__global__ __launch_bounds__(256) void k_finalize(
    const float* __restrict__ feat,
    const float* __restrict__ gam, const float* __restrict__ bet,
    const float* __restrict__ wres, const float* __restrict__ bres,
    float* __restrict__ out)
{
    int idx = blockIdx.x * 256 + threadIdx.x;
    int row = idx >> 6, c = idx & 63;
    float mu, rs;
    stats_combine(c >> 4, mu, rs);
    float x = (g_o[idx] - mu) * rs;
    x = fmaf(x, __ldg(&gam[c]), __ldg(&bet[c]));
    float a = __ldg(&bres[c]);
#pragma unroll
    for (int k4 = 0; k4 < 4; k4++) {
        float4 f = __ldg((const float4*)&feat[row*16 + k4*4]);
        float4 w = __ldg((const float4*)&wres[c*16 + k4*4]);
        a = fmaf(f.x,w.x,a); a = fmaf(f.y,w.y,a); a = fmaf(f.z,w.z,a); a = fmaf(f.w,w.w,a);
    }
    out[idx] = x + a;
}

extern "C" void kernel_launch(void* const* d_in, const int* in_sizes, int n_in,
                              void* d_out, int out_size)
{
    const float* points   = (const float*)d_in[0];
    const float* nuv      = (const float*)d_in[1];
    const float* features = (const float*)d_in[2];
    const float* w_in1    = (const float*)d_in[3];
    const float* b_in1    = (const float*)d_in[4];
    const float* w_in2    = (const float*)d_in[5];
    const float* b_in2    = (const float*)d_in[6];
    const float* g_in     = (const float*)d_in[7];
    const float* be_in    = (const float*)d_in[8];
    const float* wq       = (const float*)d_in[9];
    const float* bq       = (const float*)d_in[10];
    const float* wk       = (const float*)d_in[11];
    const float* bk       = (const float*)d_in[12];
    const float* wv       = (const float*)d_in[13];
    const float* bv       = (const float*)d_in[14];
    const float* conv_w1  = (const float*)d_in[15];
    const float* conv_b1  = (const float*)d_in[16];
    const float* conv_w2  = (const float*)d_in[17];
    const float* conv_b2  = (const float*)d_in[18];
    const float* rls      = (const float*)d_in[19];
    const float* rbf_a    = (const float*)d_in[20];
    const float* rbf_b    = (const float*)d_in[21];
    const float* rbf_c    = (const float*)d_in[22];
    const float* w_o1     = (const float*)d_in[23];
    const float* b_o1     = (const float*)d_in[24];
    const float* w_o2     = (const float*)d_in[25];
    const float* b_o2     = (const float*)d_in[26];
    const float* g_out    = (const float*)d_in[27];
    const float* be_out   = (const float*)d_in[28];
    const float* w_res    = (const float*)d_in[29];
    const float* b_res    = (const float*)d_in[30];

    k_in_mlp<<<NPTS/4, 256>>>(features, w_in1, b_in1, w_in2, b_in2);
    k_stats_part<<<NPART, 256>>>(0, points, nuv);
    k_qkv<<<NPTS/4, 256>>>(wq, bq, wk, bk, wv, bv, g_in, be_in);
    k_attn<<<NPTS, 256>>>(points, nuv, conv_w1, conv_b1, conv_w2, conv_b2,
                          rls, rbf_a, rbf_b, rbf_c);
    k_out_mlp<<<NPTS/4, 256>>>(w_o1, b_o1, w_o2, b_o2);
    k_stats_part<<<NPART, 256>>>(1, points, nuv);
    k_finalize<<<NPTS*64/256, 256>>>(features, g_out, be_out, w_res, b_res, (float*)d_out);
}